// round 3
// baseline (speedup 1.0000x reference)
#include <cuda_runtime.h>
#include <math.h>

#define D 128
#define NN 50000
#define NE 640000

// ---- scratch (device globals: allocation-free) ----
__device__ float g_h0[NN * D];      // h0, later reused for t2
__device__ float g_short[NN * D];   // shortcut
__device__ float g_mean[NN * D];    // mean aggregation buffer
__device__ float g_t[NN * D];       // t1 / h1 (in-place LN)
__device__ int   g_deg[NN];
__device__ int   g_cursor[NN];
__device__ int   g_rp[NN + 1];
__device__ int   g_col[NE];

__device__ __forceinline__ float gelu_f(float x) {
    return 0.5f * x * (1.0f + erff(x * 0.70710678118654752f));
}

// ---------------- CSR build ----------------
__global__ void zero_deg_kernel(int n) {
    int i = blockIdx.x * blockDim.x + threadIdx.x;
    if (i < n) g_deg[i] = 0;
}

__global__ void hist_kernel(const int* __restrict__ dst, int e_cnt) {
    int e = blockIdx.x * blockDim.x + threadIdx.x;
    if (e < e_cnt) atomicAdd(&g_deg[dst[e]], 1);
}

// single-block chunked exclusive scan over degrees -> row_ptr + cursor
__global__ void scan_kernel(int n) {
    __shared__ int warpsums[32];
    __shared__ int s_carry;
    int tid = threadIdx.x;
    if (tid == 0) { s_carry = 0; g_rp[0] = 0; }
    __syncthreads();
    for (int base = 0; base < n; base += 1024) {
        int i = base + tid;
        int v = (i < n) ? g_deg[i] : 0;
        int x = v;
        #pragma unroll
        for (int off = 1; off < 32; off <<= 1) {
            int t = __shfl_up_sync(0xFFFFFFFFu, x, off);
            if ((tid & 31) >= off) x += t;
        }
        if ((tid & 31) == 31) warpsums[tid >> 5] = x;
        __syncthreads();
        if (tid < 32) {
            int w = warpsums[tid];
            #pragma unroll
            for (int off = 1; off < 32; off <<= 1) {
                int t = __shfl_up_sync(0xFFFFFFFFu, w, off);
                if (tid >= off) w += t;
            }
            warpsums[tid] = w;
        }
        __syncthreads();
        int incl = x + ((tid >= 32) ? warpsums[(tid >> 5) - 1] : 0) + s_carry;
        if (i < n) { g_rp[i + 1] = incl; g_cursor[i] = incl - v; }
        __syncthreads();
        if (tid == 1023) s_carry = incl;
        __syncthreads();
    }
}

__global__ void fill_kernel(const int* __restrict__ src, const int* __restrict__ dst, int e_cnt) {
    int e = blockIdx.x * blockDim.x + threadIdx.x;
    if (e < e_cnt) {
        int d = dst[e];
        int p = atomicAdd(&g_cursor[d], 1);
        g_col[p] = src[e];
    }
}

// ---------------- mean aggregation: warp per destination node ----------------
__global__ void agg_kernel(const float* __restrict__ h, float* __restrict__ meanout, int n) {
    int w = (int)((blockIdx.x * blockDim.x + threadIdx.x) >> 5);
    int lane = threadIdx.x & 31;
    if (w >= n) return;
    int s = g_rp[w], e = g_rp[w + 1];
    float4 acc = make_float4(0.f, 0.f, 0.f, 0.f);
    for (int i = s; i < e; i++) {
        int srcn = __ldg(&g_col[i]);
        float4 v = __ldg((const float4*)(h + (size_t)srcn * D) + lane);
        acc.x += v.x; acc.y += v.y; acc.z += v.z; acc.w += v.w;
    }
    float inv = 1.0f / (float)max(e - s, 1);
    acc.x *= inv; acc.y *= inv; acc.z *= inv; acc.w *= inv;
    *((float4*)(meanout + (size_t)w * D) + lane) = acc;
}

// ---------------- tiled matmul: out[M,128] = A0@W0^T (+ A1@W1^T) + bias, optional GELU ----------------
// BM=64, full K=128 per phase. 256 threads; thread computes 8x4 micro-tile.
// smem: xsT[128][64] (K-major) + wsT[128][128] (K-major) = 96 KB dynamic.
__global__ void mm_kernel(const float* __restrict__ A0, const float* __restrict__ W0,
                          const float* __restrict__ A1, const float* __restrict__ W1,
                          const float* __restrict__ bias, float* __restrict__ out,
                          int M, int act) {
    extern __shared__ float smem[];
    float* xsT = smem;              // [k][m], stride 64
    float* wsT = smem + 128 * 64;   // [k][j], stride 128
    int tid = threadIdx.x;
    int m0 = blockIdx.x * 64;
    int tx = tid & 31;   // output cols tx*4 .. tx*4+3
    int ty = tid >> 5;   // output rows m0 + ty*8 .. +7

    float acc[8][4];
    #pragma unroll
    for (int i = 0; i < 8; i++)
        #pragma unroll
        for (int j = 0; j < 4; j++) acc[i][j] = 0.f;

    int nph = (A1 != nullptr) ? 2 : 1;
    for (int ph = 0; ph < nph; ph++) {
        const float* A = ph ? A1 : A0;
        const float* W = ph ? W1 : W0;
        __syncthreads();
        {   // A tile -> xsT (transposed store: lanes hit consecutive banks)
            int m = tid & 63, kq = tid >> 6;   // kq in 0..3, covers k = kq*32..+31
            int gm = m0 + m;
            const float4* ap = (const float4*)(A + (size_t)gm * D + kq * 32);
            #pragma unroll
            for (int i = 0; i < 8; i++) {
                float4 v = (gm < M) ? __ldg(ap + i) : make_float4(0.f, 0.f, 0.f, 0.f);
                int k = kq * 32 + i * 4;
                xsT[(k + 0) * 64 + m] = v.x;
                xsT[(k + 1) * 64 + m] = v.y;
                xsT[(k + 2) * 64 + m] = v.z;
                xsT[(k + 3) * 64 + m] = v.w;
            }
        }
        {   // W -> wsT (transposed)
            int j = tid & 127, kh = tid >> 7;  // kh in 0..1, covers k = kh*64..+63
            const float4* wp = (const float4*)(W + (size_t)j * D + kh * 64);
            #pragma unroll
            for (int i = 0; i < 16; i++) {
                float4 v = __ldg(wp + i);
                int k = kh * 64 + i * 4;
                wsT[(k + 0) * 128 + j] = v.x;
                wsT[(k + 1) * 128 + j] = v.y;
                wsT[(k + 2) * 128 + j] = v.z;
                wsT[(k + 3) * 128 + j] = v.w;
            }
        }
        __syncthreads();
        #pragma unroll 4
        for (int k = 0; k < D; k++) {
            float4 a0 = *(const float4*)&xsT[k * 64 + ty * 8];      // broadcast within warp
            float4 a1 = *(const float4*)&xsT[k * 64 + ty * 8 + 4];  // broadcast
            float4 b  = *(const float4*)&wsT[k * 128 + tx * 4];     // conflict-free
            float am[8] = {a0.x, a0.y, a0.z, a0.w, a1.x, a1.y, a1.z, a1.w};
            #pragma unroll
            for (int i = 0; i < 8; i++) {
                acc[i][0] += am[i] * b.x;
                acc[i][1] += am[i] * b.y;
                acc[i][2] += am[i] * b.z;
                acc[i][3] += am[i] * b.w;
            }
        }
    }
    float4 bv = __ldg((const float4*)bias + tx);
    #pragma unroll
    for (int i = 0; i < 8; i++) {
        int gm = m0 + ty * 8 + i;
        if (gm < M) {
            float4 o;
            o.x = acc[i][0] + bv.x;
            o.y = acc[i][1] + bv.y;
            o.z = acc[i][2] + bv.z;
            o.w = acc[i][3] + bv.w;
            if (act) {
                o.x = gelu_f(o.x); o.y = gelu_f(o.y);
                o.z = gelu_f(o.z); o.w = gelu_f(o.w);
            }
            *(float4*)(out + (size_t)gm * D + tx * 4) = o;
        }
    }
}

// ---------------- layernorm (+ optional shortcut add) + GELU: warp per row ----------------
// mode 1: out = gelu(ln(in))          mode 2: out = gelu(ln(in) + sc)
__global__ void ln_kernel(const float* __restrict__ in, const float* __restrict__ gamma,
                          const float* __restrict__ beta, const float* __restrict__ sc,
                          float* __restrict__ out, int n, int mode) {
    int w = (int)((blockIdx.x * blockDim.x + threadIdx.x) >> 5);
    int lane = threadIdx.x & 31;
    if (w >= n) return;
    float4 v = __ldg((const float4*)(in + (size_t)w * D) + lane);
    float s = v.x + v.y + v.z + v.w;
    #pragma unroll
    for (int off = 16; off; off >>= 1) s += __shfl_xor_sync(0xFFFFFFFFu, s, off);
    float mu = s * (1.0f / 128.0f);
    float dx = v.x - mu, dy = v.y - mu, dz = v.z - mu, dw = v.w - mu;
    float q = dx * dx + dy * dy + dz * dz + dw * dw;
    #pragma unroll
    for (int off = 16; off; off >>= 1) q += __shfl_xor_sync(0xFFFFFFFFu, q, off);
    float r = rsqrtf(q * (1.0f / 128.0f) + 1e-5f);
    float4 g = __ldg((const float4*)gamma + lane);
    float4 b = __ldg((const float4*)beta + lane);
    float4 o;
    o.x = dx * r * g.x + b.x;
    o.y = dy * r * g.y + b.y;
    o.z = dz * r * g.z + b.z;
    o.w = dw * r * g.w + b.w;
    if (mode == 2) {
        float4 scv = __ldg((const float4*)(sc + (size_t)w * D) + lane);
        o.x += scv.x; o.y += scv.y; o.z += scv.z; o.w += scv.w;
    }
    o.x = gelu_f(o.x); o.y = gelu_f(o.y); o.z = gelu_f(o.z); o.w = gelu_f(o.w);
    *((float4*)(out + (size_t)w * D) + lane) = o;
}

extern "C" void kernel_launch(void* const* d_in, const int* in_sizes, int n_in,
                              void* d_out, int out_size) {
    const float* x     = (const float*)d_in[0];
    const int*   edges = (const int*)  d_in[1];
    const float* dp_w  = (const float*)d_in[2];
    const float* dp_b  = (const float*)d_in[3];
    const float* sc_w  = (const float*)d_in[4];
    const float* sc_b  = (const float*)d_in[5];
    const float* g1_lw = (const float*)d_in[6];
    const float* g1_lb = (const float*)d_in[7];
    const float* g1_rw = (const float*)d_in[8];
    const float* n1_g  = (const float*)d_in[9];
    const float* n1_b  = (const float*)d_in[10];
    const float* g2_lw = (const float*)d_in[11];
    const float* g2_lb = (const float*)d_in[12];
    const float* g2_rw = (const float*)d_in[13];
    const float* n2_g  = (const float*)d_in[14];
    const float* n2_b  = (const float*)d_in[15];
    float* out = (float*)d_out;

    int M = in_sizes[0] / D;      // 50000
    int E = in_sizes[1] / 2;      // 640000
    const int* srcp = edges;
    const int* dstp = edges + E;

    float *h0, *shrt, *meanb, *tb;
    cudaGetSymbolAddress((void**)&h0,    g_h0);
    cudaGetSymbolAddress((void**)&shrt,  g_short);
    cudaGetSymbolAddress((void**)&meanb, g_mean);
    cudaGetSymbolAddress((void**)&tb,    g_t);

    const int MM_SMEM = (128 * 64 + 128 * 128) * (int)sizeof(float);  // 96 KB
    cudaFuncSetAttribute(mm_kernel, cudaFuncAttributeMaxDynamicSharedMemorySize, MM_SMEM);

    int nblk = (M + 63) / 64;
    int wgrid = (M * 32 + 255) / 256;

    // CSR build (shared by both SAGE layers)
    zero_deg_kernel<<<(M + 255) / 256, 256>>>(M);
    hist_kernel<<<(E + 255) / 256, 256>>>(dstp, E);
    scan_kernel<<<1, 1024>>>(M);
    fill_kernel<<<(E + 255) / 256, 256>>>(srcp, dstp, E);

    // h0 = gelu(x @ dp_w^T + dp_b) ; shortcut = x @ sc_w^T + sc_b
    mm_kernel<<<nblk, 256, MM_SMEM>>>(x, dp_w, nullptr, nullptr, dp_b, h0, M, 1);
    mm_kernel<<<nblk, 256, MM_SMEM>>>(x, sc_w, nullptr, nullptr, sc_b, shrt, M, 0);

    // SAGE 1: t1 = mean(h0) @ g1_lw^T + g1_lb + h0 @ g1_rw^T
    agg_kernel<<<wgrid, 256>>>(h0, meanb, M);
    mm_kernel<<<nblk, 256, MM_SMEM>>>(meanb, g1_lw, h0, g1_rw, g1_lb, tb, M, 0);
    // h1 = gelu(ln(t1))  (in-place)
    ln_kernel<<<wgrid, 256>>>(tb, n1_g, n1_b, nullptr, tb, M, 1);

    // SAGE 2: t2 = mean(h1) @ g2_lw^T + g2_lb + h1 @ g2_rw^T   (t2 -> g_h0, now free)
    agg_kernel<<<wgrid, 256>>>(tb, meanb, M);
    mm_kernel<<<nblk, 256, MM_SMEM>>>(meanb, g2_lw, tb, g2_rw, g2_lb, h0, M, 0);

    // out = gelu(ln(t2) + shortcut)
    ln_kernel<<<wgrid, 256>>>(h0, n2_g, n2_b, shrt, out, M, 2);
}

// round 4
// speedup vs baseline: 1.8756x; 1.8756x over previous
#include <cuda_runtime.h>
#include <math.h>

#define D 128
#define NN 50000
#define NE 640000

// ---- scratch (device globals: allocation-free) ----
__device__ float g_h0[NN * D];      // h0, later reused for t2
__device__ float g_short[NN * D];   // shortcut
__device__ float g_mean[NN * D];    // mean aggregation buffer
__device__ float g_t[NN * D];       // t1 / h1 (in-place LN)
__device__ int   g_deg[NN];
__device__ int   g_cursor[NN];
__device__ int   g_rp[NN + 1];
__device__ int   g_col[NE];

__device__ __forceinline__ float gelu_f(float x) {
    return 0.5f * x * (1.0f + erff(x * 0.70710678118654752f));
}

__device__ __forceinline__ unsigned f2tf32(float x) {
    unsigned r;
    asm("cvt.rna.tf32.f32 %0, %1;" : "=r"(r) : "f"(x));
    return r;
}

__device__ __forceinline__ void mma_tf32(float* c, const unsigned* a, const unsigned* b) {
    asm volatile(
        "mma.sync.aligned.m16n8k8.row.col.f32.tf32.tf32.f32 "
        "{%0,%1,%2,%3},{%4,%5,%6,%7},{%8,%9},{%0,%1,%2,%3};"
        : "+f"(c[0]), "+f"(c[1]), "+f"(c[2]), "+f"(c[3])
        : "r"(a[0]), "r"(a[1]), "r"(a[2]), "r"(a[3]), "r"(b[0]), "r"(b[1]));
}

// ---------------- CSR build ----------------
__global__ void zero_deg_kernel(int n) {
    int i = blockIdx.x * blockDim.x + threadIdx.x;
    if (i < n) g_deg[i] = 0;
}

__global__ void hist_kernel(const int* __restrict__ dst, int e_cnt) {
    int e = blockIdx.x * blockDim.x + threadIdx.x;
    if (e < e_cnt) atomicAdd(&g_deg[dst[e]], 1);
}

// single-block chunked exclusive scan over degrees -> row_ptr + cursor
__global__ void scan_kernel(int n) {
    __shared__ int warpsums[32];
    __shared__ int s_carry;
    int tid = threadIdx.x;
    if (tid == 0) { s_carry = 0; g_rp[0] = 0; }
    __syncthreads();
    for (int base = 0; base < n; base += 1024) {
        int i = base + tid;
        int v = (i < n) ? g_deg[i] : 0;
        int x = v;
        #pragma unroll
        for (int off = 1; off < 32; off <<= 1) {
            int t = __shfl_up_sync(0xFFFFFFFFu, x, off);
            if ((tid & 31) >= off) x += t;
        }
        if ((tid & 31) == 31) warpsums[tid >> 5] = x;
        __syncthreads();
        if (tid < 32) {
            int w = warpsums[tid];
            #pragma unroll
            for (int off = 1; off < 32; off <<= 1) {
                int t = __shfl_up_sync(0xFFFFFFFFu, w, off);
                if (tid >= off) w += t;
            }
            warpsums[tid] = w;
        }
        __syncthreads();
        int incl = x + ((tid >= 32) ? warpsums[(tid >> 5) - 1] : 0) + s_carry;
        if (i < n) { g_rp[i + 1] = incl; g_cursor[i] = incl - v; }
        __syncthreads();
        if (tid == 1023) s_carry = incl;
        __syncthreads();
    }
}

__global__ void fill_kernel(const int* __restrict__ src, const int* __restrict__ dst, int e_cnt) {
    int e = blockIdx.x * blockDim.x + threadIdx.x;
    if (e < e_cnt) {
        int d = dst[e];
        int p = atomicAdd(&g_cursor[d], 1);
        g_col[p] = src[e];
    }
}

// ---------------- mean aggregation: warp per destination node ----------------
__global__ void agg_kernel(const float* __restrict__ h, float* __restrict__ meanout, int n) {
    int w = (int)((blockIdx.x * blockDim.x + threadIdx.x) >> 5);
    int lane = threadIdx.x & 31;
    if (w >= n) return;
    int s = g_rp[w], e = g_rp[w + 1];
    float4 acc = make_float4(0.f, 0.f, 0.f, 0.f);
    for (int i = s; i < e; i++) {
        int srcn = __ldg(&g_col[i]);
        float4 v = __ldg((const float4*)(h + (size_t)srcn * D) + lane);
        acc.x += v.x; acc.y += v.y; acc.z += v.z; acc.w += v.w;
    }
    float inv = 1.0f / (float)max(e - s, 1);
    acc.x *= inv; acc.y *= inv; acc.z *= inv; acc.w *= inv;
    *((float4*)(meanout + (size_t)w * D) + lane) = acc;
}

// ---------------- tf32 tensor-core matmul ----------------
// out[M,128] = A0@W0^T (+ A1@W1^T) + bias, optional GELU.
// BM=64, BN=128, full K=128 per phase. 256 threads = 8 warps in 2(m)x4(n) grid;
// each warp owns a 32x32 output tile = 2x4 m16n8k8 fragment tiles.
// smem (tf32 bit patterns): as[64][132] + ws[128][132], pad 4 => all fragment
// LDS are conflict-free (bank = (4*row+col)&31 is a lane permutation).
#define MMPAD 132
__global__ __launch_bounds__(256, 2)
void mm_kernel(const float* __restrict__ A0, const float* __restrict__ W0,
               const float* __restrict__ A1, const float* __restrict__ W1,
               const float* __restrict__ bias, float* __restrict__ out,
               int M, int act) {
    extern __shared__ unsigned smemu[];
    unsigned* as = smemu;                 // [64][132]
    unsigned* ws = smemu + 64 * MMPAD;    // [128][132]
    int tid = threadIdx.x;
    int lane = tid & 31;
    int wid = tid >> 5;
    int wm = wid & 1;        // 0..1 -> m offset wm*32
    int wn = wid >> 1;       // 0..3 -> n offset wn*32
    int m0 = blockIdx.x * 64;
    int qr = lane >> 2;      // 0..7
    int qc = lane & 3;       // 0..3

    float acc[2][4][4];
    #pragma unroll
    for (int i = 0; i < 2; i++)
        #pragma unroll
        for (int j = 0; j < 4; j++)
            #pragma unroll
            for (int k = 0; k < 4; k++) acc[i][j][k] = 0.f;

    int nph = (A1 != nullptr) ? 2 : 1;
    for (int ph = 0; ph < nph; ph++) {
        const float* A = ph ? A1 : A0;
        const float* W = ph ? W1 : W0;
        __syncthreads();
        // stage A tile [64][128] -> as (tf32)
        #pragma unroll
        for (int i = 0; i < 8; i++) {
            int idx = tid + i * 256;        // 0..2047
            int row = idx >> 5;
            int c4  = (idx & 31) * 4;
            int gm = m0 + row;
            float4 v = (gm < M) ? __ldg((const float4*)(A + (size_t)gm * D + c4))
                                : make_float4(0.f, 0.f, 0.f, 0.f);
            uint4 u = make_uint4(f2tf32(v.x), f2tf32(v.y), f2tf32(v.z), f2tf32(v.w));
            *(uint4*)&as[row * MMPAD + c4] = u;
        }
        // stage W [128][128] -> ws (tf32)
        #pragma unroll
        for (int i = 0; i < 16; i++) {
            int idx = tid + i * 256;        // 0..4095
            int row = idx >> 5;
            int c4  = (idx & 31) * 4;
            float4 v = __ldg((const float4*)(W + (size_t)row * D + c4));
            uint4 u = make_uint4(f2tf32(v.x), f2tf32(v.y), f2tf32(v.z), f2tf32(v.w));
            *(uint4*)&ws[row * MMPAD + c4] = u;
        }
        __syncthreads();

        #pragma unroll 8
        for (int ks = 0; ks < 16; ks++) {
            int k = ks * 8;
            unsigned afr[2][4];
            unsigned bfr[4][2];
            #pragma unroll
            for (int m = 0; m < 2; m++) {
                int ar = wm * 32 + m * 16 + qr;
                afr[m][0] = as[ar * MMPAD + k + qc];
                afr[m][1] = as[(ar + 8) * MMPAD + k + qc];
                afr[m][2] = as[ar * MMPAD + k + qc + 4];
                afr[m][3] = as[(ar + 8) * MMPAD + k + qc + 4];
            }
            #pragma unroll
            for (int n = 0; n < 4; n++) {
                int bc = wn * 32 + n * 8 + qr;
                bfr[n][0] = ws[bc * MMPAD + k + qc];
                bfr[n][1] = ws[bc * MMPAD + k + qc + 4];
            }
            #pragma unroll
            for (int m = 0; m < 2; m++)
                #pragma unroll
                for (int n = 0; n < 4; n++)
                    mma_tf32(acc[m][n], afr[m], bfr[n]);
        }
    }

    // epilogue: c0 at (qr, 2*qc), c1 (qr, 2*qc+1), c2/c3 at row+8
    int cpair = qc * 2;
    #pragma unroll
    for (int n = 0; n < 4; n++) {
        int col = wn * 32 + n * 8 + cpair;
        float b0 = __ldg(bias + col);
        float b1 = __ldg(bias + col + 1);
        #pragma unroll
        for (int m = 0; m < 2; m++) {
            int gr = m0 + wm * 32 + m * 16 + qr;
            if (gr < M) {
                float2 o;
                o.x = acc[m][n][0] + b0;
                o.y = acc[m][n][1] + b1;
                if (act) { o.x = gelu_f(o.x); o.y = gelu_f(o.y); }
                *(float2*)(out + (size_t)gr * D + col) = o;
            }
            if (gr + 8 < M) {
                float2 o;
                o.x = acc[m][n][2] + b0;
                o.y = acc[m][n][3] + b1;
                if (act) { o.x = gelu_f(o.x); o.y = gelu_f(o.y); }
                *(float2*)(out + (size_t)(gr + 8) * D + col) = o;
            }
        }
    }
}

// ---------------- layernorm (+ optional shortcut add) + GELU: warp per row ----------------
// mode 1: out = gelu(ln(in))          mode 2: out = gelu(ln(in) + sc)
__global__ void ln_kernel(const float* __restrict__ in, const float* __restrict__ gamma,
                          const float* __restrict__ beta, const float* __restrict__ sc,
                          float* __restrict__ out, int n, int mode) {
    int w = (int)((blockIdx.x * blockDim.x + threadIdx.x) >> 5);
    int lane = threadIdx.x & 31;
    if (w >= n) return;
    float4 v = __ldg((const float4*)(in + (size_t)w * D) + lane);
    float s = v.x + v.y + v.z + v.w;
    #pragma unroll
    for (int off = 16; off; off >>= 1) s += __shfl_xor_sync(0xFFFFFFFFu, s, off);
    float mu = s * (1.0f / 128.0f);
    float dx = v.x - mu, dy = v.y - mu, dz = v.z - mu, dw = v.w - mu;
    float q = dx * dx + dy * dy + dz * dz + dw * dw;
    #pragma unroll
    for (int off = 16; off; off >>= 1) q += __shfl_xor_sync(0xFFFFFFFFu, q, off);
    float r = rsqrtf(q * (1.0f / 128.0f) + 1e-5f);
    float4 g = __ldg((const float4*)gamma + lane);
    float4 b = __ldg((const float4*)beta + lane);
    float4 o;
    o.x = dx * r * g.x + b.x;
    o.y = dy * r * g.y + b.y;
    o.z = dz * r * g.z + b.z;
    o.w = dw * r * g.w + b.w;
    if (mode == 2) {
        float4 scv = __ldg((const float4*)(sc + (size_t)w * D) + lane);
        o.x += scv.x; o.y += scv.y; o.z += scv.z; o.w += scv.w;
    }
    o.x = gelu_f(o.x); o.y = gelu_f(o.y); o.z = gelu_f(o.z); o.w = gelu_f(o.w);
    *((float4*)(out + (size_t)w * D) + lane) = o;
}

extern "C" void kernel_launch(void* const* d_in, const int* in_sizes, int n_in,
                              void* d_out, int out_size) {
    const float* x     = (const float*)d_in[0];
    const int*   edges = (const int*)  d_in[1];
    const float* dp_w  = (const float*)d_in[2];
    const float* dp_b  = (const float*)d_in[3];
    const float* sc_w  = (const float*)d_in[4];
    const float* sc_b  = (const float*)d_in[5];
    const float* g1_lw = (const float*)d_in[6];
    const float* g1_lb = (const float*)d_in[7];
    const float* g1_rw = (const float*)d_in[8];
    const float* n1_g  = (const float*)d_in[9];
    const float* n1_b  = (const float*)d_in[10];
    const float* g2_lw = (const float*)d_in[11];
    const float* g2_lb = (const float*)d_in[12];
    const float* g2_rw = (const float*)d_in[13];
    const float* n2_g  = (const float*)d_in[14];
    const float* n2_b  = (const float*)d_in[15];
    float* out = (float*)d_out;

    int M = in_sizes[0] / D;      // 50000
    int E = in_sizes[1] / 2;      // 640000
    const int* srcp = edges;
    const int* dstp = edges + E;

    float *h0, *shrt, *meanb, *tb;
    cudaGetSymbolAddress((void**)&h0,    g_h0);
    cudaGetSymbolAddress((void**)&shrt,  g_short);
    cudaGetSymbolAddress((void**)&meanb, g_mean);
    cudaGetSymbolAddress((void**)&tb,    g_t);

    const int MM_SMEM = (64 + 128) * MMPAD * (int)sizeof(unsigned);  // 101376 B
    cudaFuncSetAttribute(mm_kernel, cudaFuncAttributeMaxDynamicSharedMemorySize, MM_SMEM);

    int nblk = (M + 63) / 64;
    int wgrid = (M * 32 + 255) / 256;

    // CSR build (shared by both SAGE layers)
    zero_deg_kernel<<<(M + 255) / 256, 256>>>(M);
    hist_kernel<<<(E + 255) / 256, 256>>>(dstp, E);
    scan_kernel<<<1, 1024>>>(M);
    fill_kernel<<<(E + 255) / 256, 256>>>(srcp, dstp, E);

    // h0 = gelu(x @ dp_w^T + dp_b) ; shortcut = x @ sc_w^T + sc_b
    mm_kernel<<<nblk, 256, MM_SMEM>>>(x, dp_w, nullptr, nullptr, dp_b, h0, M, 1);
    mm_kernel<<<nblk, 256, MM_SMEM>>>(x, sc_w, nullptr, nullptr, sc_b, shrt, M, 0);

    // SAGE 1: t1 = mean(h0) @ g1_lw^T + g1_lb + h0 @ g1_rw^T
    agg_kernel<<<wgrid, 256>>>(h0, meanb, M);
    mm_kernel<<<nblk, 256, MM_SMEM>>>(meanb, g1_lw, h0, g1_rw, g1_lb, tb, M, 0);
    // h1 = gelu(ln(t1))  (in-place)
    ln_kernel<<<wgrid, 256>>>(tb, n1_g, n1_b, nullptr, tb, M, 1);

    // SAGE 2: t2 = mean(h1) @ g2_lw^T + g2_lb + h1 @ g2_rw^T   (t2 -> g_h0, now free)
    agg_kernel<<<wgrid, 256>>>(tb, meanb, M);
    mm_kernel<<<nblk, 256, MM_SMEM>>>(meanb, g2_lw, tb, g2_rw, g2_lb, h0, M, 0);

    // out = gelu(ln(t2) + shortcut)
    ln_kernel<<<wgrid, 256>>>(h0, n2_g, n2_b, shrt, out, M, 2);
}

// round 5
// speedup vs baseline: 2.1418x; 1.1419x over previous
#include <cuda_runtime.h>
#include <math.h>

#define D 128
#define NN 50000
#define NE 640000
#define MMPAD 132

// ---- scratch (device globals: allocation-free) ----
__device__ float g_h0[NN * D];      // h0, later reused for t2
__device__ float g_short[NN * D];   // shortcut
__device__ float g_mean[NN * D];    // mean aggregation buffer
__device__ float g_t[NN * D];       // t1 / h1
__device__ int   g_deg[NN];
__device__ int   g_cursor[NN];
__device__ int   g_rp[NN + 1];
__device__ int   g_col[NE];
__device__ int   g_part[256];
__device__ int   g_poff[256];

__device__ __forceinline__ float gelu_f(float x) {
    return 0.5f * x * (1.0f + erff(x * 0.70710678118654752f));
}

__device__ __forceinline__ unsigned f2tf32(float x) {
    unsigned r;
    asm("cvt.rna.tf32.f32 %0, %1;" : "=r"(r) : "f"(x));
    return r;
}

__device__ __forceinline__ void mma_tf32(float* c, const unsigned* a, const unsigned* b) {
    asm volatile(
        "mma.sync.aligned.m16n8k8.row.col.f32.tf32.tf32.f32 "
        "{%0,%1,%2,%3},{%4,%5,%6,%7},{%8,%9},{%0,%1,%2,%3};"
        : "+f"(c[0]), "+f"(c[1]), "+f"(c[2]), "+f"(c[3])
        : "r"(a[0]), "r"(a[1]), "r"(a[2]), "r"(a[3]), "r"(b[0]), "r"(b[1]));
}

// ---------------- CSR build ----------------
__global__ void zero_deg_kernel(int n) {
    int i = blockIdx.x * blockDim.x + threadIdx.x;
    if (i < n) g_deg[i] = 0;
}

__global__ void hist_kernel(const int* __restrict__ dst, int e_cnt) {
    int base = (blockIdx.x * blockDim.x + threadIdx.x) * 4;
    if (base + 4 <= e_cnt) {
        int4 d = *(const int4*)(dst + base);
        atomicAdd(&g_deg[d.x], 1);
        atomicAdd(&g_deg[d.y], 1);
        atomicAdd(&g_deg[d.z], 1);
        atomicAdd(&g_deg[d.w], 1);
    } else {
        for (int j = 0; j < 4; j++)
            if (base + j < e_cnt) atomicAdd(&g_deg[dst[base + j]], 1);
    }
}

// pass 1: per-block partial sums of degrees
__global__ void part_kernel(int n) {
    __shared__ int wsum[8];
    int tid = threadIdx.x;
    int i = blockIdx.x * 256 + tid;
    int v = (i < n) ? g_deg[i] : 0;
    int s = v;
    #pragma unroll
    for (int off = 16; off; off >>= 1) s += __shfl_xor_sync(0xFFFFFFFFu, s, off);
    if ((tid & 31) == 0) wsum[tid >> 5] = s;
    __syncthreads();
    if (tid == 0) {
        int t = 0;
        #pragma unroll
        for (int j = 0; j < 8; j++) t += wsum[j];
        g_part[blockIdx.x] = t;
    }
}

// pass 2: exclusive scan over block partials (nb <= 256)
__global__ void scanpart_kernel(int nb) {
    __shared__ int wsum[8];
    int tid = threadIdx.x, lane = tid & 31, wid = tid >> 5;
    int v = (tid < nb) ? g_part[tid] : 0;
    int x = v;
    #pragma unroll
    for (int off = 1; off < 32; off <<= 1) {
        int t = __shfl_up_sync(0xFFFFFFFFu, x, off);
        if (lane >= off) x += t;
    }
    if (lane == 31) wsum[wid] = x;
    __syncthreads();
    if (tid < 32) {
        int w = (tid < 8) ? wsum[tid] : 0;
        #pragma unroll
        for (int off = 1; off < 8; off <<= 1) {
            int t = __shfl_up_sync(0xFFFFFFFFu, w, off);
            if (tid >= off) w += t;
        }
        if (tid < 8) wsum[tid] = w;
    }
    __syncthreads();
    int incl = x + ((wid > 0) ? wsum[wid - 1] : 0);
    if (tid < nb) g_poff[tid] = incl - v;
}

// pass 3: block-local scan + global offset -> row_ptr + cursor
__global__ void apply_kernel(int n) {
    __shared__ int wsum[8];
    int tid = threadIdx.x, lane = tid & 31, wid = tid >> 5;
    int i = blockIdx.x * 256 + tid;
    int v = (i < n) ? g_deg[i] : 0;
    int x = v;
    #pragma unroll
    for (int off = 1; off < 32; off <<= 1) {
        int t = __shfl_up_sync(0xFFFFFFFFu, x, off);
        if (lane >= off) x += t;
    }
    if (lane == 31) wsum[wid] = x;
    __syncthreads();
    if (tid < 32) {
        int w = (tid < 8) ? wsum[tid] : 0;
        #pragma unroll
        for (int off = 1; off < 8; off <<= 1) {
            int t = __shfl_up_sync(0xFFFFFFFFu, w, off);
            if (tid >= off) w += t;
        }
        if (tid < 8) wsum[tid] = w;
    }
    __syncthreads();
    int incl = x + ((wid > 0) ? wsum[wid - 1] : 0) + g_poff[blockIdx.x];
    if (i < n) { g_rp[i + 1] = incl; g_cursor[i] = incl - v; }
    if (i == 0) g_rp[0] = 0;
}

__global__ void fill_kernel(const int* __restrict__ src, const int* __restrict__ dst, int e_cnt) {
    int base = (blockIdx.x * blockDim.x + threadIdx.x) * 4;
    if (base + 4 <= e_cnt) {
        int4 s = *(const int4*)(src + base);
        int4 d = *(const int4*)(dst + base);
        g_col[atomicAdd(&g_cursor[d.x], 1)] = s.x;
        g_col[atomicAdd(&g_cursor[d.y], 1)] = s.y;
        g_col[atomicAdd(&g_cursor[d.z], 1)] = s.z;
        g_col[atomicAdd(&g_cursor[d.w], 1)] = s.w;
    } else {
        for (int j = 0; j < 4; j++)
            if (base + j < e_cnt) {
                int dd = dst[base + j];
                int p = atomicAdd(&g_cursor[dd], 1);
                g_col[p] = src[base + j];
            }
    }
}

// ---------------- mean aggregation: warp per destination node ----------------
__global__ void agg_kernel(const float* __restrict__ h, float* __restrict__ meanout, int n) {
    int w = (int)((blockIdx.x * blockDim.x + threadIdx.x) >> 5);
    int lane = threadIdx.x & 31;
    if (w >= n) return;
    int s = g_rp[w], e = g_rp[w + 1];
    float4 acc = make_float4(0.f, 0.f, 0.f, 0.f);
    for (int i = s; i < e; i++) {
        int srcn = __ldg(&g_col[i]);
        float4 v = __ldg((const float4*)(h + (size_t)srcn * D) + lane);
        acc.x += v.x; acc.y += v.y; acc.z += v.z; acc.w += v.w;
    }
    float inv = 1.0f / (float)max(e - s, 1);
    acc.x *= inv; acc.y *= inv; acc.z *= inv; acc.w *= inv;
    *((float4*)(meanout + (size_t)w * D) + lane) = acc;
}

// ---------------- staging helpers (tf32) ----------------
__device__ __forceinline__ void stage_A(unsigned* as, const float* A, int m0, int M, int tid) {
    #pragma unroll
    for (int i = 0; i < 8; i++) {
        int idx = tid + i * 256;
        int row = idx >> 5;
        int c4  = (idx & 31) * 4;
        int gm = m0 + row;
        float4 v = (gm < M) ? __ldg((const float4*)(A + (size_t)gm * D + c4))
                            : make_float4(0.f, 0.f, 0.f, 0.f);
        uint4 u = make_uint4(f2tf32(v.x), f2tf32(v.y), f2tf32(v.z), f2tf32(v.w));
        *(uint4*)&as[row * MMPAD + c4] = u;
    }
}
__device__ __forceinline__ void stage_W(unsigned* ws, const float* W, int tid) {
    #pragma unroll
    for (int i = 0; i < 16; i++) {
        int idx = tid + i * 256;
        int row = idx >> 5;
        int c4  = (idx & 31) * 4;
        float4 v = __ldg((const float4*)(W + (size_t)row * D + c4));
        uint4 u = make_uint4(f2tf32(v.x), f2tf32(v.y), f2tf32(v.z), f2tf32(v.w));
        *(uint4*)&ws[row * MMPAD + c4] = u;
    }
}

// ---------------- mm_dual: out0 = gelu(A@W0^T+b0), out1 = A@W1^T+b1 ----------------
// stages A once, loops over the two weight matrices.
__global__ __launch_bounds__(256, 2)
void mm_dual_kernel(const float* __restrict__ A,
                    const float* __restrict__ W0, const float* __restrict__ b0v,
                    const float* __restrict__ W1, const float* __restrict__ b1v,
                    float* __restrict__ out0, float* __restrict__ out1, int M) {
    extern __shared__ unsigned smemu[];
    unsigned* as = smemu;
    unsigned* ws = smemu + 64 * MMPAD;
    int tid = threadIdx.x, lane = tid & 31, wid = tid >> 5;
    int wm = wid & 1, wn = wid >> 1;
    int m0 = blockIdx.x * 64;
    int qr = lane >> 2, qc = lane & 3;

    float acc[2][2][4][4];
    #pragma unroll
    for (int w = 0; w < 2; w++)
        #pragma unroll
        for (int i = 0; i < 2; i++)
            #pragma unroll
            for (int j = 0; j < 4; j++)
                #pragma unroll
                for (int k = 0; k < 4; k++) acc[w][i][j][k] = 0.f;

    stage_A(as, A, m0, M, tid);
    #pragma unroll
    for (int w = 0; w < 2; w++) {
        if (w) __syncthreads();           // ws readers done before overwrite
        stage_W(ws, w ? W1 : W0, tid);
        __syncthreads();
        #pragma unroll 8
        for (int ks = 0; ks < 16; ks++) {
            int k = ks * 8;
            unsigned afr[2][4], bfr[4][2];
            #pragma unroll
            for (int m = 0; m < 2; m++) {
                int ar = wm * 32 + m * 16 + qr;
                afr[m][0] = as[ar * MMPAD + k + qc];
                afr[m][1] = as[(ar + 8) * MMPAD + k + qc];
                afr[m][2] = as[ar * MMPAD + k + qc + 4];
                afr[m][3] = as[(ar + 8) * MMPAD + k + qc + 4];
            }
            #pragma unroll
            for (int n = 0; n < 4; n++) {
                int bc = wn * 32 + n * 8 + qr;
                bfr[n][0] = ws[bc * MMPAD + k + qc];
                bfr[n][1] = ws[bc * MMPAD + k + qc + 4];
            }
            #pragma unroll
            for (int m = 0; m < 2; m++)
                #pragma unroll
                for (int n = 0; n < 4; n++)
                    mma_tf32(acc[w][m][n], afr[m], bfr[n]);
        }
    }

    int cpair = qc * 2;
    #pragma unroll
    for (int n = 0; n < 4; n++) {
        int col = wn * 32 + n * 8 + cpair;
        float b00 = __ldg(b0v + col), b01 = __ldg(b0v + col + 1);
        float b10 = __ldg(b1v + col), b11 = __ldg(b1v + col + 1);
        #pragma unroll
        for (int m = 0; m < 2; m++) {
            int gr = m0 + wm * 32 + m * 16 + qr;
            if (gr < M) {
                float2 o0 = make_float2(gelu_f(acc[0][m][n][0] + b00),
                                        gelu_f(acc[0][m][n][1] + b01));
                float2 o1 = make_float2(acc[1][m][n][0] + b10, acc[1][m][n][1] + b11);
                *(float2*)(out0 + (size_t)gr * D + col) = o0;
                *(float2*)(out1 + (size_t)gr * D + col) = o1;
            }
            if (gr + 8 < M) {
                float2 o0 = make_float2(gelu_f(acc[0][m][n][2] + b00),
                                        gelu_f(acc[0][m][n][3] + b01));
                float2 o1 = make_float2(acc[1][m][n][2] + b10, acc[1][m][n][3] + b11);
                *(float2*)(out0 + (size_t)(gr + 8) * D + col) = o0;
                *(float2*)(out1 + (size_t)(gr + 8) * D + col) = o1;
            }
        }
    }
}

// ---------------- mm_sage: out = epi( A0@W0^T + A1@W1^T + bias ) ----------------
// epi = LN(gamma,beta) [+ sc] then GELU, fused via smem tile (BN=128 = full row).
__global__ __launch_bounds__(256, 2)
void mm_sage_kernel(const float* __restrict__ A0, const float* __restrict__ W0,
                    const float* __restrict__ A1, const float* __restrict__ W1,
                    const float* __restrict__ bias,
                    const float* __restrict__ gamma, const float* __restrict__ beta,
                    const float* __restrict__ sc,
                    float* __restrict__ out, int M) {
    extern __shared__ unsigned smemu[];
    unsigned* as = smemu;
    unsigned* ws = smemu + 64 * MMPAD;
    int tid = threadIdx.x, lane = tid & 31, wid = tid >> 5;
    int wm = wid & 1, wn = wid >> 1;
    int m0 = blockIdx.x * 64;
    int qr = lane >> 2, qc = lane & 3;

    float acc[2][4][4];
    #pragma unroll
    for (int i = 0; i < 2; i++)
        #pragma unroll
        for (int j = 0; j < 4; j++)
            #pragma unroll
            for (int k = 0; k < 4; k++) acc[i][j][k] = 0.f;

    #pragma unroll
    for (int ph = 0; ph < 2; ph++) {
        if (ph) __syncthreads();
        stage_A(as, ph ? A1 : A0, m0, M, tid);
        stage_W(ws, ph ? W1 : W0, tid);
        __syncthreads();
        #pragma unroll 8
        for (int ks = 0; ks < 16; ks++) {
            int k = ks * 8;
            unsigned afr[2][4], bfr[4][2];
            #pragma unroll
            for (int m = 0; m < 2; m++) {
                int ar = wm * 32 + m * 16 + qr;
                afr[m][0] = as[ar * MMPAD + k + qc];
                afr[m][1] = as[(ar + 8) * MMPAD + k + qc];
                afr[m][2] = as[ar * MMPAD + k + qc + 4];
                afr[m][3] = as[(ar + 8) * MMPAD + k + qc + 4];
            }
            #pragma unroll
            for (int n = 0; n < 4; n++) {
                int bc = wn * 32 + n * 8 + qr;
                bfr[n][0] = ws[bc * MMPAD + k + qc];
                bfr[n][1] = ws[bc * MMPAD + k + qc + 4];
            }
            #pragma unroll
            for (int m = 0; m < 2; m++)
                #pragma unroll
                for (int n = 0; n < 4; n++)
                    mma_tf32(acc[m][n], afr[m], bfr[n]);
        }
    }

    // spill tile (+bias) to smem, then warp-per-row LN epilogue
    float* os = (float*)smemu;   // reuse, [64][MMPAD]
    __syncthreads();
    int cpair = qc * 2;
    #pragma unroll
    for (int n = 0; n < 4; n++) {
        int col = wn * 32 + n * 8 + cpair;
        float b0 = __ldg(bias + col), b1 = __ldg(bias + col + 1);
        #pragma unroll
        for (int m = 0; m < 2; m++) {
            int r = wm * 32 + m * 16 + qr;
            os[r * MMPAD + col]           = acc[m][n][0] + b0;
            os[r * MMPAD + col + 1]       = acc[m][n][1] + b1;
            os[(r + 8) * MMPAD + col]     = acc[m][n][2] + b0;
            os[(r + 8) * MMPAD + col + 1] = acc[m][n][3] + b1;
        }
    }
    __syncthreads();

    float4 g = __ldg((const float4*)gamma + lane);
    float4 bb = __ldg((const float4*)beta + lane);
    for (int rr = wid; rr < 64; rr += 8) {
        int gr = m0 + rr;
        if (gr >= M) break;
        float4 v = *(const float4*)&os[rr * MMPAD + lane * 4];
        float s = v.x + v.y + v.z + v.w;
        #pragma unroll
        for (int off = 16; off; off >>= 1) s += __shfl_xor_sync(0xFFFFFFFFu, s, off);
        float mu = s * (1.0f / 128.0f);
        float dx = v.x - mu, dy = v.y - mu, dz = v.z - mu, dw = v.w - mu;
        float q = dx * dx + dy * dy + dz * dz + dw * dw;
        #pragma unroll
        for (int off = 16; off; off >>= 1) q += __shfl_xor_sync(0xFFFFFFFFu, q, off);
        float r = rsqrtf(q * (1.0f / 128.0f) + 1e-5f);
        float4 o;
        o.x = dx * r * g.x + bb.x;
        o.y = dy * r * g.y + bb.y;
        o.z = dz * r * g.z + bb.z;
        o.w = dw * r * g.w + bb.w;
        if (sc != nullptr) {
            float4 scv = __ldg((const float4*)(sc + (size_t)gr * D) + lane);
            o.x += scv.x; o.y += scv.y; o.z += scv.z; o.w += scv.w;
        }
        o.x = gelu_f(o.x); o.y = gelu_f(o.y); o.z = gelu_f(o.z); o.w = gelu_f(o.w);
        *(float4*)(out + (size_t)gr * D + lane * 4) = o;
    }
}

extern "C" void kernel_launch(void* const* d_in, const int* in_sizes, int n_in,
                              void* d_out, int out_size) {
    const float* x     = (const float*)d_in[0];
    const int*   edges = (const int*)  d_in[1];
    const float* dp_w  = (const float*)d_in[2];
    const float* dp_b  = (const float*)d_in[3];
    const float* sc_w  = (const float*)d_in[4];
    const float* sc_b  = (const float*)d_in[5];
    const float* g1_lw = (const float*)d_in[6];
    const float* g1_lb = (const float*)d_in[7];
    const float* g1_rw = (const float*)d_in[8];
    const float* n1_g  = (const float*)d_in[9];
    const float* n1_b  = (const float*)d_in[10];
    const float* g2_lw = (const float*)d_in[11];
    const float* g2_lb = (const float*)d_in[12];
    const float* g2_rw = (const float*)d_in[13];
    const float* n2_g  = (const float*)d_in[14];
    const float* n2_b  = (const float*)d_in[15];
    float* out = (float*)d_out;

    int M = in_sizes[0] / D;      // 50000
    int E = in_sizes[1] / 2;      // 640000
    const int* srcp = edges;
    const int* dstp = edges + E;

    float *h0, *shrt, *meanb, *tb;
    cudaGetSymbolAddress((void**)&h0,    g_h0);
    cudaGetSymbolAddress((void**)&shrt,  g_short);
    cudaGetSymbolAddress((void**)&meanb, g_mean);
    cudaGetSymbolAddress((void**)&tb,    g_t);

    const int MM_SMEM = (64 + 128) * MMPAD * (int)sizeof(unsigned);  // 101376 B
    cudaFuncSetAttribute(mm_dual_kernel, cudaFuncAttributeMaxDynamicSharedMemorySize, MM_SMEM);
    cudaFuncSetAttribute(mm_sage_kernel, cudaFuncAttributeMaxDynamicSharedMemorySize, MM_SMEM);

    int nblk = (M + 63) / 64;
    int wgrid = (M * 32 + 255) / 256;
    int nb256 = (M + 255) / 256;
    int egrid4 = (E + 1023) / 1024;

    // CSR build (shared by both SAGE layers)
    zero_deg_kernel<<<nb256, 256>>>(M);
    hist_kernel<<<egrid4, 256>>>(dstp, E);
    part_kernel<<<nb256, 256>>>(M);
    scanpart_kernel<<<1, 256>>>(nb256);
    apply_kernel<<<nb256, 256>>>(M);
    fill_kernel<<<egrid4, 256>>>(srcp, dstp, E);

    // h0 = gelu(x @ dp_w^T + dp_b) ; shortcut = x @ sc_w^T + sc_b  (A staged once)
    mm_dual_kernel<<<nblk, 256, MM_SMEM>>>(x, dp_w, dp_b, sc_w, sc_b, h0, shrt, M);

    // SAGE 1 + LN + GELU fused
    agg_kernel<<<wgrid, 256>>>(h0, meanb, M);
    mm_sage_kernel<<<nblk, 256, MM_SMEM>>>(meanb, g1_lw, h0, g1_rw, g1_lb,
                                           n1_g, n1_b, nullptr, tb, M);

    // SAGE 2 + LN + shortcut + GELU fused
    agg_kernel<<<wgrid, 256>>>(tb, meanb, M);
    mm_sage_kernel<<<nblk, 256, MM_SMEM>>>(meanb, g2_lw, tb, g2_rw, g2_lb,
                                           n2_g, n2_b, shrt, out, M);
}

// round 6
// speedup vs baseline: 2.5748x; 1.2022x over previous
#include <cuda_runtime.h>
#include <cuda_fp16.h>
#include <math.h>

#define D 128
#define NN 50000
#define NE 640000
#define MMPAD 132
#define KPAD 136   // halves per row in fp16 staging (128 + 8 pad)

// ---- scratch (device globals: allocation-free) ----
__device__ float g_h0[NN * D];      // h0, later reused for t2
__device__ float g_short[NN * D];   // shortcut
__device__ float g_mean[NN * D];    // mean aggregation buffer
__device__ float g_t[NN * D];       // t1 / h1
__device__ int   g_deg[NN];
__device__ int   g_cursor[NN];
__device__ int   g_rp[NN + 1];
__device__ int   g_col[NE];
__device__ unsigned long long g_desc[256];   // lookback descriptors

__device__ __forceinline__ float gelu_f(float x) {
    return 0.5f * x * (1.0f + erff(x * 0.70710678118654752f));
}

__device__ __forceinline__ unsigned f2h2(float a, float b) {
    __half2 h = __floats2half2_rn(a, b);
    return *(unsigned*)&h;
}

__device__ __forceinline__ void mma_f16(float* c, const unsigned* a, const unsigned* b) {
    asm volatile(
        "mma.sync.aligned.m16n8k16.row.col.f32.f16.f16.f32 "
        "{%0,%1,%2,%3},{%4,%5,%6,%7},{%8,%9},{%0,%1,%2,%3};"
        : "+f"(c[0]), "+f"(c[1]), "+f"(c[2]), "+f"(c[3])
        : "r"(a[0]), "r"(a[1]), "r"(a[2]), "r"(a[3]), "r"(b[0]), "r"(b[1]));
}

// ---------------- CSR build ----------------
__global__ void zero_kernel(int n) {
    int i = blockIdx.x * blockDim.x + threadIdx.x;
    if (i < n) g_deg[i] = 0;
    if (i < 256) g_desc[i] = 0ULL;
}

__global__ void hist_kernel(const int* __restrict__ dst, int e_cnt) {
    int base = (blockIdx.x * blockDim.x + threadIdx.x) * 4;
    if (base + 4 <= e_cnt) {
        int4 d = *(const int4*)(dst + base);
        atomicAdd(&g_deg[d.x], 1);
        atomicAdd(&g_deg[d.y], 1);
        atomicAdd(&g_deg[d.z], 1);
        atomicAdd(&g_deg[d.w], 1);
    } else {
        for (int j = 0; j < 4; j++)
            if (base + j < e_cnt) atomicAdd(&g_deg[dst[base + j]], 1);
    }
}

// single-pass scan with warp-parallel decoupled lookback.
// grid = ceil(n/256) blocks (<=256), 256 threads.
__global__ void scan_lookback_kernel(int n) {
    __shared__ int wsum[8];
    __shared__ int s_total;
    __shared__ int s_excl;
    int tid = threadIdx.x, lane = tid & 31, wid = tid >> 5;
    int bid = blockIdx.x;
    int i = bid * 256 + tid;
    int v = (i < n) ? g_deg[i] : 0;
    // block-local inclusive scan
    int x = v;
    #pragma unroll
    for (int off = 1; off < 32; off <<= 1) {
        int t = __shfl_up_sync(0xFFFFFFFFu, x, off);
        if (lane >= off) x += t;
    }
    if (lane == 31) wsum[wid] = x;
    __syncthreads();
    if (tid < 32) {
        int w = (tid < 8) ? wsum[tid] : 0;
        #pragma unroll
        for (int off = 1; off < 8; off <<= 1) {
            int t = __shfl_up_sync(0xFFFFFFFFu, w, off);
            if (tid >= off) w += t;
        }
        if (tid < 8) wsum[tid] = w;
    }
    __syncthreads();
    int incl = x + ((wid > 0) ? wsum[wid - 1] : 0);
    if (tid == 255) { s_total = incl; }
    __syncthreads();
    int total = s_total;

    // publish aggregate (block 0 publishes full prefix immediately)
    if (tid == 0) {
        __threadfence();
        unsigned long long st = (bid == 0) ? (2ULL << 32) : (1ULL << 32);
        atomicExch(&g_desc[bid], st | (unsigned)total);
        if (bid == 0) s_excl = 0;
    }
    // warp 0 does the lookback
    if (bid > 0 && wid == 0) {
        int j = bid - 1 - lane;
        long ex = 0;
        while (true) {
            unsigned long long d;
            unsigned st;
            if (j >= 0) {
                do { d = atomicAdd(&g_desc[j], 0ULL); st = (unsigned)(d >> 32); } while (st == 0);
            } else {
                d = (2ULL << 32); st = 2u;
            }
            unsigned mask = __ballot_sync(0xFFFFFFFFu, st == 2u);
            if (mask) {
                int firstP = __ffs(mask) - 1;   // nearest block with full prefix
                unsigned contrib = (lane <= firstP) ? (unsigned)d : 0u;
                #pragma unroll
                for (int off = 16; off; off >>= 1)
                    contrib += __shfl_xor_sync(0xFFFFFFFFu, contrib, off);
                ex += (long)contrib;
                break;
            } else {
                unsigned contrib = (unsigned)d;
                #pragma unroll
                for (int off = 16; off; off >>= 1)
                    contrib += __shfl_xor_sync(0xFFFFFFFFu, contrib, off);
                ex += (long)contrib;
                j -= 32;
            }
        }
        if (lane == 0) {
            __threadfence();
            atomicExch(&g_desc[bid], (2ULL << 32) | (unsigned)(ex + total));
            s_excl = (int)ex;
        }
    }
    __syncthreads();
    int off = s_excl;
    if (i < n) {
        int gincl = incl + off;
        g_rp[i + 1] = gincl;
        g_cursor[i] = gincl - v;
    }
    if (i == 0) g_rp[0] = 0;
}

__global__ void fill_kernel(const int* __restrict__ src, const int* __restrict__ dst, int e_cnt) {
    int base = (blockIdx.x * blockDim.x + threadIdx.x) * 4;
    if (base + 4 <= e_cnt) {
        int4 s = *(const int4*)(src + base);
        int4 d = *(const int4*)(dst + base);
        g_col[atomicAdd(&g_cursor[d.x], 1)] = s.x;
        g_col[atomicAdd(&g_cursor[d.y], 1)] = s.y;
        g_col[atomicAdd(&g_cursor[d.z], 1)] = s.z;
        g_col[atomicAdd(&g_cursor[d.w], 1)] = s.w;
    } else {
        for (int j = 0; j < 4; j++)
            if (base + j < e_cnt) {
                int dd = dst[base + j];
                int p = atomicAdd(&g_cursor[dd], 1);
                g_col[p] = src[base + j];
            }
    }
}

// ---------------- mean aggregation: warp per destination node ----------------
__global__ void agg_kernel(const float* __restrict__ h, float* __restrict__ meanout, int n) {
    int w = (int)((blockIdx.x * blockDim.x + threadIdx.x) >> 5);
    int lane = threadIdx.x & 31;
    if (w >= n) return;
    int s = g_rp[w], e = g_rp[w + 1];
    float4 acc = make_float4(0.f, 0.f, 0.f, 0.f);
    for (int i = s; i < e; i++) {
        int srcn = __ldg(&g_col[i]);
        float4 v = __ldg((const float4*)(h + (size_t)srcn * D) + lane);
        acc.x += v.x; acc.y += v.y; acc.z += v.z; acc.w += v.w;
    }
    float inv = 1.0f / (float)max(e - s, 1);
    acc.x *= inv; acc.y *= inv; acc.z *= inv; acc.w *= inv;
    *((float4*)(meanout + (size_t)w * D) + lane) = acc;
}

// ---------------- staging helpers (fp32 -> half2 smem) ----------------
__device__ __forceinline__ void stage_A(__half* as, const float* A, int m0, int M, int tid) {
    #pragma unroll
    for (int i = 0; i < 8; i++) {
        int idx = tid + i * 256;
        int row = idx >> 5;
        int c4  = (idx & 31) * 4;
        int gm = m0 + row;
        float4 v = (gm < M) ? __ldg((const float4*)(A + (size_t)gm * D + c4))
                            : make_float4(0.f, 0.f, 0.f, 0.f);
        uint2 u = make_uint2(f2h2(v.x, v.y), f2h2(v.z, v.w));
        *(uint2*)(&as[row * KPAD + c4]) = u;
    }
}
__device__ __forceinline__ void stage_W(__half* ws, const float* W, int tid) {
    #pragma unroll
    for (int i = 0; i < 16; i++) {
        int idx = tid + i * 256;
        int row = idx >> 5;
        int c4  = (idx & 31) * 4;
        float4 v = __ldg((const float4*)(W + (size_t)row * D + c4));
        uint2 u = make_uint2(f2h2(v.x, v.y), f2h2(v.z, v.w));
        *(uint2*)(&ws[row * KPAD + c4]) = u;
    }
}

// fragment loads for m16n8k16 (row.col), half2-packed smem, stride KPAD
__device__ __forceinline__ void load_afr(unsigned* afr, const __half* as, int ar, int k, int qc) {
    afr[0] = *(const unsigned*)&as[ar * KPAD + k + 2 * qc];
    afr[1] = *(const unsigned*)&as[(ar + 8) * KPAD + k + 2 * qc];
    afr[2] = *(const unsigned*)&as[ar * KPAD + k + 2 * qc + 8];
    afr[3] = *(const unsigned*)&as[(ar + 8) * KPAD + k + 2 * qc + 8];
}
__device__ __forceinline__ void load_bfr(unsigned* bfr, const __half* ws, int bc, int k, int qc) {
    bfr[0] = *(const unsigned*)&ws[bc * KPAD + k + 2 * qc];
    bfr[1] = *(const unsigned*)&ws[bc * KPAD + k + 2 * qc + 8];
}

// ---------------- mm_dual: out0 = gelu(A@W0^T+b0), out1 = A@W1^T+b1 ----------------
__global__ __launch_bounds__(256, 2)
void mm_dual_kernel(const float* __restrict__ A,
                    const float* __restrict__ W0, const float* __restrict__ b0v,
                    const float* __restrict__ W1, const float* __restrict__ b1v,
                    float* __restrict__ out0, float* __restrict__ out1, int M) {
    extern __shared__ __half smemh[];
    __half* as = smemh;                 // [64][KPAD]
    __half* ws = smemh + 64 * KPAD;     // [128][KPAD]
    int tid = threadIdx.x, lane = tid & 31, wid = tid >> 5;
    int wm = wid & 1, wn = wid >> 1;
    int m0 = blockIdx.x * 64;
    int qr = lane >> 2, qc = lane & 3;

    float acc[2][2][4][4];
    #pragma unroll
    for (int w = 0; w < 2; w++)
        #pragma unroll
        for (int i = 0; i < 2; i++)
            #pragma unroll
            for (int j = 0; j < 4; j++)
                #pragma unroll
                for (int k = 0; k < 4; k++) acc[w][i][j][k] = 0.f;

    stage_A(as, A, m0, M, tid);
    #pragma unroll
    for (int w = 0; w < 2; w++) {
        if (w) __syncthreads();
        stage_W(ws, w ? W1 : W0, tid);
        __syncthreads();
        #pragma unroll
        for (int ks = 0; ks < 8; ks++) {
            int k = ks * 16;
            unsigned afr[2][4], bfr[4][2];
            #pragma unroll
            for (int m = 0; m < 2; m++)
                load_afr(afr[m], as, wm * 32 + m * 16 + qr, k, qc);
            #pragma unroll
            for (int n = 0; n < 4; n++)
                load_bfr(bfr[n], ws, wn * 32 + n * 8 + qr, k, qc);
            #pragma unroll
            for (int m = 0; m < 2; m++)
                #pragma unroll
                for (int n = 0; n < 4; n++)
                    mma_f16(acc[w][m][n], afr[m], bfr[n]);
        }
    }

    int cpair = qc * 2;
    #pragma unroll
    for (int n = 0; n < 4; n++) {
        int col = wn * 32 + n * 8 + cpair;
        float b00 = __ldg(b0v + col), b01 = __ldg(b0v + col + 1);
        float b10 = __ldg(b1v + col), b11 = __ldg(b1v + col + 1);
        #pragma unroll
        for (int m = 0; m < 2; m++) {
            int gr = m0 + wm * 32 + m * 16 + qr;
            if (gr < M) {
                float2 o0 = make_float2(gelu_f(acc[0][m][n][0] + b00),
                                        gelu_f(acc[0][m][n][1] + b01));
                float2 o1 = make_float2(acc[1][m][n][0] + b10, acc[1][m][n][1] + b11);
                *(float2*)(out0 + (size_t)gr * D + col) = o0;
                *(float2*)(out1 + (size_t)gr * D + col) = o1;
            }
            if (gr + 8 < M) {
                float2 o0 = make_float2(gelu_f(acc[0][m][n][2] + b00),
                                        gelu_f(acc[0][m][n][3] + b01));
                float2 o1 = make_float2(acc[1][m][n][2] + b10, acc[1][m][n][3] + b11);
                *(float2*)(out0 + (size_t)(gr + 8) * D + col) = o0;
                *(float2*)(out1 + (size_t)(gr + 8) * D + col) = o1;
            }
        }
    }
}

// ---------------- mm_sage: out = gelu( LN( A0@W0^T + A1@W1^T + bias ) [+ sc] ) ----------------
__global__ __launch_bounds__(256, 2)
void mm_sage_kernel(const float* __restrict__ A0, const float* __restrict__ W0,
                    const float* __restrict__ A1, const float* __restrict__ W1,
                    const float* __restrict__ bias,
                    const float* __restrict__ gamma, const float* __restrict__ beta,
                    const float* __restrict__ sc,
                    float* __restrict__ out, int M) {
    extern __shared__ __half smemh[];
    __half* as = smemh;
    __half* ws = smemh + 64 * KPAD;
    int tid = threadIdx.x, lane = tid & 31, wid = tid >> 5;
    int wm = wid & 1, wn = wid >> 1;
    int m0 = blockIdx.x * 64;
    int qr = lane >> 2, qc = lane & 3;

    float acc[2][4][4];
    #pragma unroll
    for (int i = 0; i < 2; i++)
        #pragma unroll
        for (int j = 0; j < 4; j++)
            #pragma unroll
            for (int k = 0; k < 4; k++) acc[i][j][k] = 0.f;

    #pragma unroll
    for (int ph = 0; ph < 2; ph++) {
        if (ph) __syncthreads();
        stage_A(as, ph ? A1 : A0, m0, M, tid);
        stage_W(ws, ph ? W1 : W0, tid);
        __syncthreads();
        #pragma unroll
        for (int ks = 0; ks < 8; ks++) {
            int k = ks * 16;
            unsigned afr[2][4], bfr[4][2];
            #pragma unroll
            for (int m = 0; m < 2; m++)
                load_afr(afr[m], as, wm * 32 + m * 16 + qr, k, qc);
            #pragma unroll
            for (int n = 0; n < 4; n++)
                load_bfr(bfr[n], ws, wn * 32 + n * 8 + qr, k, qc);
            #pragma unroll
            for (int m = 0; m < 2; m++)
                #pragma unroll
                for (int n = 0; n < 4; n++)
                    mma_f16(acc[m][n], afr[m], bfr[n]);
        }
    }

    // spill tile (+bias) to smem as fp32, then warp-per-row LN epilogue
    float* os = (float*)smemh;   // reuse, [64][MMPAD] fp32 (33792 B <= 52224 B)
    __syncthreads();
    int cpair = qc * 2;
    #pragma unroll
    for (int n = 0; n < 4; n++) {
        int col = wn * 32 + n * 8 + cpair;
        float b0 = __ldg(bias + col), b1 = __ldg(bias + col + 1);
        #pragma unroll
        for (int m = 0; m < 2; m++) {
            int r = wm * 32 + m * 16 + qr;
            os[r * MMPAD + col]           = acc[m][n][0] + b0;
            os[r * MMPAD + col + 1]       = acc[m][n][1] + b1;
            os[(r + 8) * MMPAD + col]     = acc[m][n][2] + b0;
            os[(r + 8) * MMPAD + col + 1] = acc[m][n][3] + b1;
        }
    }
    __syncthreads();

    float4 g = __ldg((const float4*)gamma + lane);
    float4 bb = __ldg((const float4*)beta + lane);
    for (int rr = wid; rr < 64; rr += 8) {
        int gr = m0 + rr;
        if (gr >= M) break;
        float4 v = *(const float4*)&os[rr * MMPAD + lane * 4];
        float s = v.x + v.y + v.z + v.w;
        #pragma unroll
        for (int off = 16; off; off >>= 1) s += __shfl_xor_sync(0xFFFFFFFFu, s, off);
        float mu = s * (1.0f / 128.0f);
        float dx = v.x - mu, dy = v.y - mu, dz = v.z - mu, dw = v.w - mu;
        float q = dx * dx + dy * dy + dz * dz + dw * dw;
        #pragma unroll
        for (int off = 16; off; off >>= 1) q += __shfl_xor_sync(0xFFFFFFFFu, q, off);
        float r = rsqrtf(q * (1.0f / 128.0f) + 1e-5f);
        float4 o;
        o.x = dx * r * g.x + bb.x;
        o.y = dy * r * g.y + bb.y;
        o.z = dz * r * g.z + bb.z;
        o.w = dw * r * g.w + bb.w;
        if (sc != nullptr) {
            float4 scv = __ldg((const float4*)(sc + (size_t)gr * D) + lane);
            o.x += scv.x; o.y += scv.y; o.z += scv.z; o.w += scv.w;
        }
        o.x = gelu_f(o.x); o.y = gelu_f(o.y); o.z = gelu_f(o.z); o.w = gelu_f(o.w);
        *(float4*)(out + (size_t)gr * D + lane * 4) = o;
    }
}

extern "C" void kernel_launch(void* const* d_in, const int* in_sizes, int n_in,
                              void* d_out, int out_size) {
    const float* x     = (const float*)d_in[0];
    const int*   edges = (const int*)  d_in[1];
    const float* dp_w  = (const float*)d_in[2];
    const float* dp_b  = (const float*)d_in[3];
    const float* sc_w  = (const float*)d_in[4];
    const float* sc_b  = (const float*)d_in[5];
    const float* g1_lw = (const float*)d_in[6];
    const float* g1_lb = (const float*)d_in[7];
    const float* g1_rw = (const float*)d_in[8];
    const float* n1_g  = (const float*)d_in[9];
    const float* n1_b  = (const float*)d_in[10];
    const float* g2_lw = (const float*)d_in[11];
    const float* g2_lb = (const float*)d_in[12];
    const float* g2_rw = (const float*)d_in[13];
    const float* n2_g  = (const float*)d_in[14];
    const float* n2_b  = (const float*)d_in[15];
    float* out = (float*)d_out;

    int M = in_sizes[0] / D;      // 50000
    int E = in_sizes[1] / 2;      // 640000
    const int* srcp = edges;
    const int* dstp = edges + E;

    float *h0, *shrt, *meanb, *tb;
    cudaGetSymbolAddress((void**)&h0,    g_h0);
    cudaGetSymbolAddress((void**)&shrt,  g_short);
    cudaGetSymbolAddress((void**)&meanb, g_mean);
    cudaGetSymbolAddress((void**)&tb,    g_t);

    const int MM_SMEM = (64 + 128) * KPAD * (int)sizeof(__half);  // 52224 B
    cudaFuncSetAttribute(mm_dual_kernel, cudaFuncAttributeMaxDynamicSharedMemorySize, MM_SMEM);
    cudaFuncSetAttribute(mm_sage_kernel, cudaFuncAttributeMaxDynamicSharedMemorySize, MM_SMEM);

    int nblk = (M + 63) / 64;
    int wgrid = (M * 32 + 255) / 256;
    int nb256 = (M + 255) / 256;
    int egrid4 = (E + 1023) / 1024;

    // CSR build (shared by both SAGE layers)
    zero_kernel<<<nb256, 256>>>(M);
    hist_kernel<<<egrid4, 256>>>(dstp, E);
    scan_lookback_kernel<<<nb256, 256>>>(M);
    fill_kernel<<<egrid4, 256>>>(srcp, dstp, E);

    // h0 = gelu(x @ dp_w^T + dp_b) ; shortcut = x @ sc_w^T + sc_b  (A staged once)
    mm_dual_kernel<<<nblk, 256, MM_SMEM>>>(x, dp_w, dp_b, sc_w, sc_b, h0, shrt, M);

    // SAGE 1 + LN + GELU fused
    agg_kernel<<<wgrid, 256>>>(h0, meanb, M);
    mm_sage_kernel<<<nblk, 256, MM_SMEM>>>(meanb, g1_lw, h0, g1_rw, g1_lb,
                                           n1_g, n1_b, nullptr, tb, M);

    // SAGE 2 + LN + shortcut + GELU fused
    agg_kernel<<<wgrid, 256>>>(tb, meanb, M);
    mm_sage_kernel<<<nblk, 256, MM_SMEM>>>(meanb, g2_lw, tb, g2_rw, g2_lb,
                                           n2_g, n2_b, shrt, out, M);
}

// round 7
// speedup vs baseline: 2.8612x; 1.1112x over previous
#include <cuda_runtime.h>
#include <cuda_fp16.h>
#include <math.h>

#define D 128
#define NN 50000
#define NE 640000
#define MMPAD 132
#define KPAD 136   // halves per row in fp16 staging (128 + 8 pad)

// ---- scratch (device globals: allocation-free) ----
__device__ __half g_h0[NN * D];     // h0 (fp16)
__device__ float  g_short[NN * D];  // shortcut (fp32: feeds output directly)
__device__ __half g_mean[NN * D];   // mean aggregation buffer (fp16)
__device__ __half g_t[NN * D];      // h1 (fp16)
__device__ int    g_deg[NN];
__device__ int    g_cursor[NN];
__device__ int    g_rp[NN + 1];
__device__ int    g_col[NE];
__device__ unsigned long long g_desc[256];   // lookback descriptors

__device__ __forceinline__ float gelu_f(float x) {
    return 0.5f * x * (1.0f + erff(x * 0.70710678118654752f));
}

__device__ __forceinline__ unsigned f2h2(float a, float b) {
    __half2 h = __floats2half2_rn(a, b);
    return *(unsigned*)&h;
}

__device__ __forceinline__ void mma_f16(float* c, const unsigned* a, const unsigned* b) {
    asm volatile(
        "mma.sync.aligned.m16n8k16.row.col.f32.f16.f16.f32 "
        "{%0,%1,%2,%3},{%4,%5,%6,%7},{%8,%9},{%0,%1,%2,%3};"
        : "+f"(c[0]), "+f"(c[1]), "+f"(c[2]), "+f"(c[3])
        : "r"(a[0]), "r"(a[1]), "r"(a[2]), "r"(a[3]), "r"(b[0]), "r"(b[1]));
}

// ---------------- CSR build ----------------
__global__ void zero_kernel(int n) {
    int i = blockIdx.x * blockDim.x + threadIdx.x;
    if (i < n) g_deg[i] = 0;
    if (i < 256) g_desc[i] = 0ULL;
}

__global__ void hist_kernel(const int* __restrict__ dst, int e_cnt) {
    int base = (blockIdx.x * blockDim.x + threadIdx.x) * 4;
    if (base + 4 <= e_cnt) {
        int4 d = *(const int4*)(dst + base);
        atomicAdd(&g_deg[d.x], 1);
        atomicAdd(&g_deg[d.y], 1);
        atomicAdd(&g_deg[d.z], 1);
        atomicAdd(&g_deg[d.w], 1);
    } else {
        for (int j = 0; j < 4; j++)
            if (base + j < e_cnt) atomicAdd(&g_deg[dst[base + j]], 1);
    }
}

// single-pass scan with warp-parallel decoupled lookback
__global__ void scan_lookback_kernel(int n) {
    __shared__ int wsum[8];
    __shared__ int s_total;
    __shared__ int s_excl;
    int tid = threadIdx.x, lane = tid & 31, wid = tid >> 5;
    int bid = blockIdx.x;
    int i = bid * 256 + tid;
    int v = (i < n) ? g_deg[i] : 0;
    int x = v;
    #pragma unroll
    for (int off = 1; off < 32; off <<= 1) {
        int t = __shfl_up_sync(0xFFFFFFFFu, x, off);
        if (lane >= off) x += t;
    }
    if (lane == 31) wsum[wid] = x;
    __syncthreads();
    if (tid < 32) {
        int w = (tid < 8) ? wsum[tid] : 0;
        #pragma unroll
        for (int off = 1; off < 8; off <<= 1) {
            int t = __shfl_up_sync(0xFFFFFFFFu, w, off);
            if (tid >= off) w += t;
        }
        if (tid < 8) wsum[tid] = w;
    }
    __syncthreads();
    int incl = x + ((wid > 0) ? wsum[wid - 1] : 0);
    if (tid == 255) { s_total = incl; }
    __syncthreads();
    int total = s_total;

    if (tid == 0) {
        __threadfence();
        unsigned long long st = (bid == 0) ? (2ULL << 32) : (1ULL << 32);
        atomicExch(&g_desc[bid], st | (unsigned)total);
        if (bid == 0) s_excl = 0;
    }
    if (bid > 0 && wid == 0) {
        int j = bid - 1 - lane;
        long ex = 0;
        while (true) {
            unsigned long long d;
            unsigned st;
            if (j >= 0) {
                do { d = atomicAdd(&g_desc[j], 0ULL); st = (unsigned)(d >> 32); } while (st == 0);
            } else {
                d = (2ULL << 32); st = 2u;
            }
            unsigned mask = __ballot_sync(0xFFFFFFFFu, st == 2u);
            if (mask) {
                int firstP = __ffs(mask) - 1;
                unsigned contrib = (lane <= firstP) ? (unsigned)d : 0u;
                #pragma unroll
                for (int off = 16; off; off >>= 1)
                    contrib += __shfl_xor_sync(0xFFFFFFFFu, contrib, off);
                ex += (long)contrib;
                break;
            } else {
                unsigned contrib = (unsigned)d;
                #pragma unroll
                for (int off = 16; off; off >>= 1)
                    contrib += __shfl_xor_sync(0xFFFFFFFFu, contrib, off);
                ex += (long)contrib;
                j -= 32;
            }
        }
        if (lane == 0) {
            __threadfence();
            atomicExch(&g_desc[bid], (2ULL << 32) | (unsigned)(ex + total));
            s_excl = (int)ex;
        }
    }
    __syncthreads();
    int off = s_excl;
    if (i < n) {
        int gincl = incl + off;
        g_rp[i + 1] = gincl;
        g_cursor[i] = gincl - v;
    }
    if (i == 0) g_rp[0] = 0;
}

__global__ void fill_kernel(const int* __restrict__ src, const int* __restrict__ dst, int e_cnt) {
    int base = (blockIdx.x * blockDim.x + threadIdx.x) * 4;
    if (base + 4 <= e_cnt) {
        int4 s = *(const int4*)(src + base);
        int4 d = *(const int4*)(dst + base);
        g_col[atomicAdd(&g_cursor[d.x], 1)] = s.x;
        g_col[atomicAdd(&g_cursor[d.y], 1)] = s.y;
        g_col[atomicAdd(&g_cursor[d.z], 1)] = s.z;
        g_col[atomicAdd(&g_cursor[d.w], 1)] = s.w;
    } else {
        for (int j = 0; j < 4; j++)
            if (base + j < e_cnt) {
                int dd = dst[base + j];
                int p = atomicAdd(&g_cursor[dd], 1);
                g_col[p] = src[base + j];
            }
    }
}

// ---------------- mean aggregation: warp per destination node (fp16 rows) ----------------
__global__ void agg_kernel(const __half* __restrict__ h, __half* __restrict__ meanout, int n) {
    int w = (int)((blockIdx.x * blockDim.x + threadIdx.x) >> 5);
    int lane = threadIdx.x & 31;
    if (w >= n) return;
    int s = g_rp[w], e = g_rp[w + 1];
    float a0 = 0.f, a1 = 0.f, a2 = 0.f, a3 = 0.f;
    for (int i = s; i < e; i++) {
        int srcn = __ldg(&g_col[i]);
        uint2 u = __ldg((const uint2*)(h + (size_t)srcn * D) + lane);
        float2 f0 = __half22float2(*(__half2*)&u.x);
        float2 f1 = __half22float2(*(__half2*)&u.y);
        a0 += f0.x; a1 += f0.y; a2 += f1.x; a3 += f1.y;
    }
    float inv = 1.0f / (float)max(e - s, 1);
    uint2 o;
    o.x = f2h2(a0 * inv, a1 * inv);
    o.y = f2h2(a2 * inv, a3 * inv);
    *((uint2*)(meanout + (size_t)w * D) + lane) = o;
}

// ---------------- staging helpers ----------------
// fp32 source -> half2 smem
__device__ __forceinline__ void stage_A(__half* as, const float* A, int m0, int M, int tid) {
    #pragma unroll
    for (int i = 0; i < 8; i++) {
        int idx = tid + i * 256;
        int row = idx >> 5;
        int c4  = (idx & 31) * 4;
        int gm = m0 + row;
        float4 v = (gm < M) ? __ldg((const float4*)(A + (size_t)gm * D + c4))
                            : make_float4(0.f, 0.f, 0.f, 0.f);
        uint2 u = make_uint2(f2h2(v.x, v.y), f2h2(v.z, v.w));
        *(uint2*)(&as[row * KPAD + c4]) = u;
    }
}
// fp16 source -> smem (straight copy)
__device__ __forceinline__ void stage_Ah(__half* as, const __half* A, int m0, int M, int tid) {
    #pragma unroll
    for (int i = 0; i < 4; i++) {
        int idx = tid + i * 256;        // 0..1023
        int row = idx >> 4;
        int c8  = (idx & 15) * 8;
        int gm = m0 + row;
        uint4 u = (gm < M) ? __ldg((const uint4*)(A + (size_t)gm * D + c8))
                           : make_uint4(0u, 0u, 0u, 0u);
        *(uint4*)(&as[row * KPAD + c8]) = u;
    }
}
__device__ __forceinline__ void stage_W(__half* ws, const float* W, int tid) {
    #pragma unroll
    for (int i = 0; i < 16; i++) {
        int idx = tid + i * 256;
        int row = idx >> 5;
        int c4  = (idx & 31) * 4;
        float4 v = __ldg((const float4*)(W + (size_t)row * D + c4));
        uint2 u = make_uint2(f2h2(v.x, v.y), f2h2(v.z, v.w));
        *(uint2*)(&ws[row * KPAD + c4]) = u;
    }
}

__device__ __forceinline__ void load_afr(unsigned* afr, const __half* as, int ar, int k, int qc) {
    afr[0] = *(const unsigned*)&as[ar * KPAD + k + 2 * qc];
    afr[1] = *(const unsigned*)&as[(ar + 8) * KPAD + k + 2 * qc];
    afr[2] = *(const unsigned*)&as[ar * KPAD + k + 2 * qc + 8];
    afr[3] = *(const unsigned*)&as[(ar + 8) * KPAD + k + 2 * qc + 8];
}
__device__ __forceinline__ void load_bfr(unsigned* bfr, const __half* ws, int bc, int k, int qc) {
    bfr[0] = *(const unsigned*)&ws[bc * KPAD + k + 2 * qc];
    bfr[1] = *(const unsigned*)&ws[bc * KPAD + k + 2 * qc + 8];
}

// ---------------- mm_dual: out0(h0,fp16) = gelu(A@W0^T+b0), out1(shortcut,fp32) = A@W1^T+b1 ----------------
__global__ __launch_bounds__(256, 2)
void mm_dual_kernel(const float* __restrict__ A,
                    const float* __restrict__ W0, const float* __restrict__ b0v,
                    const float* __restrict__ W1, const float* __restrict__ b1v,
                    __half* __restrict__ out0, float* __restrict__ out1, int M) {
    extern __shared__ __half smemh[];
    __half* as = smemh;
    __half* ws = smemh + 64 * KPAD;
    int tid = threadIdx.x, lane = tid & 31, wid = tid >> 5;
    int wm = wid & 1, wn = wid >> 1;
    int m0 = blockIdx.x * 64;
    int qr = lane >> 2, qc = lane & 3;

    float acc[2][2][4][4];
    #pragma unroll
    for (int w = 0; w < 2; w++)
        #pragma unroll
        for (int i = 0; i < 2; i++)
            #pragma unroll
            for (int j = 0; j < 4; j++)
                #pragma unroll
                for (int k = 0; k < 4; k++) acc[w][i][j][k] = 0.f;

    stage_A(as, A, m0, M, tid);
    #pragma unroll
    for (int w = 0; w < 2; w++) {
        if (w) __syncthreads();
        stage_W(ws, w ? W1 : W0, tid);
        __syncthreads();
        #pragma unroll
        for (int ks = 0; ks < 8; ks++) {
            int k = ks * 16;
            unsigned afr[2][4], bfr[4][2];
            #pragma unroll
            for (int m = 0; m < 2; m++)
                load_afr(afr[m], as, wm * 32 + m * 16 + qr, k, qc);
            #pragma unroll
            for (int n = 0; n < 4; n++)
                load_bfr(bfr[n], ws, wn * 32 + n * 8 + qr, k, qc);
            #pragma unroll
            for (int m = 0; m < 2; m++)
                #pragma unroll
                for (int n = 0; n < 4; n++)
                    mma_f16(acc[w][m][n], afr[m], bfr[n]);
        }
    }

    int cpair = qc * 2;
    #pragma unroll
    for (int n = 0; n < 4; n++) {
        int col = wn * 32 + n * 8 + cpair;
        float b00 = __ldg(b0v + col), b01 = __ldg(b0v + col + 1);
        float b10 = __ldg(b1v + col), b11 = __ldg(b1v + col + 1);
        #pragma unroll
        for (int m = 0; m < 2; m++) {
            int gr = m0 + wm * 32 + m * 16 + qr;
            if (gr < M) {
                *(unsigned*)(out0 + (size_t)gr * D + col) =
                    f2h2(gelu_f(acc[0][m][n][0] + b00), gelu_f(acc[0][m][n][1] + b01));
                float2 o1 = make_float2(acc[1][m][n][0] + b10, acc[1][m][n][1] + b11);
                *(float2*)(out1 + (size_t)gr * D + col) = o1;
            }
            if (gr + 8 < M) {
                *(unsigned*)(out0 + (size_t)(gr + 8) * D + col) =
                    f2h2(gelu_f(acc[0][m][n][2] + b00), gelu_f(acc[0][m][n][3] + b01));
                float2 o1 = make_float2(acc[1][m][n][2] + b10, acc[1][m][n][3] + b11);
                *(float2*)(out1 + (size_t)(gr + 8) * D + col) = o1;
            }
        }
    }
}

// ---------------- mm_sage: out = gelu( LN( A0@W0^T + A1@W1^T + bias ) [+ sc] ) ----------------
// A0, A1 are fp16. OUT_HALF selects fp16 (h1) vs fp32 (final d_out) output.
template <bool OUT_HALF>
__global__ __launch_bounds__(256, 2)
void mm_sage_kernel(const __half* __restrict__ A0, const float* __restrict__ W0,
                    const __half* __restrict__ A1, const float* __restrict__ W1,
                    const float* __restrict__ bias,
                    const float* __restrict__ gamma, const float* __restrict__ beta,
                    const float* __restrict__ sc,
                    void* __restrict__ outp, int M) {
    extern __shared__ __half smemh[];
    __half* as = smemh;
    __half* ws = smemh + 64 * KPAD;
    int tid = threadIdx.x, lane = tid & 31, wid = tid >> 5;
    int wm = wid & 1, wn = wid >> 1;
    int m0 = blockIdx.x * 64;
    int qr = lane >> 2, qc = lane & 3;

    float acc[2][4][4];
    #pragma unroll
    for (int i = 0; i < 2; i++)
        #pragma unroll
        for (int j = 0; j < 4; j++)
            #pragma unroll
            for (int k = 0; k < 4; k++) acc[i][j][k] = 0.f;

    #pragma unroll
    for (int ph = 0; ph < 2; ph++) {
        if (ph) __syncthreads();
        stage_Ah(as, ph ? A1 : A0, m0, M, tid);
        stage_W(ws, ph ? W1 : W0, tid);
        __syncthreads();
        #pragma unroll
        for (int ks = 0; ks < 8; ks++) {
            int k = ks * 16;
            unsigned afr[2][4], bfr[4][2];
            #pragma unroll
            for (int m = 0; m < 2; m++)
                load_afr(afr[m], as, wm * 32 + m * 16 + qr, k, qc);
            #pragma unroll
            for (int n = 0; n < 4; n++)
                load_bfr(bfr[n], ws, wn * 32 + n * 8 + qr, k, qc);
            #pragma unroll
            for (int m = 0; m < 2; m++)
                #pragma unroll
                for (int n = 0; n < 4; n++)
                    mma_f16(acc[m][n], afr[m], bfr[n]);
        }
    }

    // spill tile (+bias) to smem as fp32, then warp-per-row LN epilogue
    float* os = (float*)smemh;   // reuse, [64][MMPAD] fp32 (33792 B <= 52224 B)
    __syncthreads();
    int cpair = qc * 2;
    #pragma unroll
    for (int n = 0; n < 4; n++) {
        int col = wn * 32 + n * 8 + cpair;
        float b0 = __ldg(bias + col), b1 = __ldg(bias + col + 1);
        #pragma unroll
        for (int m = 0; m < 2; m++) {
            int r = wm * 32 + m * 16 + qr;
            os[r * MMPAD + col]           = acc[m][n][0] + b0;
            os[r * MMPAD + col + 1]       = acc[m][n][1] + b1;
            os[(r + 8) * MMPAD + col]     = acc[m][n][2] + b0;
            os[(r + 8) * MMPAD + col + 1] = acc[m][n][3] + b1;
        }
    }
    __syncthreads();

    float4 g = __ldg((const float4*)gamma + lane);
    float4 bb = __ldg((const float4*)beta + lane);
    for (int rr = wid; rr < 64; rr += 8) {
        int gr = m0 + rr;
        if (gr >= M) break;
        float4 v = *(const float4*)&os[rr * MMPAD + lane * 4];
        float s = v.x + v.y + v.z + v.w;
        #pragma unroll
        for (int off = 16; off; off >>= 1) s += __shfl_xor_sync(0xFFFFFFFFu, s, off);
        float mu = s * (1.0f / 128.0f);
        float dx = v.x - mu, dy = v.y - mu, dz = v.z - mu, dw = v.w - mu;
        float q = dx * dx + dy * dy + dz * dz + dw * dw;
        #pragma unroll
        for (int off = 16; off; off >>= 1) q += __shfl_xor_sync(0xFFFFFFFFu, q, off);
        float r = rsqrtf(q * (1.0f / 128.0f) + 1e-5f);
        float4 o;
        o.x = dx * r * g.x + bb.x;
        o.y = dy * r * g.y + bb.y;
        o.z = dz * r * g.z + bb.z;
        o.w = dw * r * g.w + bb.w;
        if (sc != nullptr) {
            float4 scv = __ldg((const float4*)(sc + (size_t)gr * D) + lane);
            o.x += scv.x; o.y += scv.y; o.z += scv.z; o.w += scv.w;
        }
        o.x = gelu_f(o.x); o.y = gelu_f(o.y); o.z = gelu_f(o.z); o.w = gelu_f(o.w);
        if (OUT_HALF) {
            __half* oh = (__half*)outp;
            uint2 u;
            u.x = f2h2(o.x, o.y);
            u.y = f2h2(o.z, o.w);
            *((uint2*)(oh + (size_t)gr * D) + lane) = u;
        } else {
            float* of = (float*)outp;
            *(float4*)(of + (size_t)gr * D + lane * 4) = o;
        }
    }
}

extern "C" void kernel_launch(void* const* d_in, const int* in_sizes, int n_in,
                              void* d_out, int out_size) {
    const float* x     = (const float*)d_in[0];
    const int*   edges = (const int*)  d_in[1];
    const float* dp_w  = (const float*)d_in[2];
    const float* dp_b  = (const float*)d_in[3];
    const float* sc_w  = (const float*)d_in[4];
    const float* sc_b  = (const float*)d_in[5];
    const float* g1_lw = (const float*)d_in[6];
    const float* g1_lb = (const float*)d_in[7];
    const float* g1_rw = (const float*)d_in[8];
    const float* n1_g  = (const float*)d_in[9];
    const float* n1_b  = (const float*)d_in[10];
    const float* g2_lw = (const float*)d_in[11];
    const float* g2_lb = (const float*)d_in[12];
    const float* g2_rw = (const float*)d_in[13];
    const float* n2_g  = (const float*)d_in[14];
    const float* n2_b  = (const float*)d_in[15];
    float* out = (float*)d_out;

    int M = in_sizes[0] / D;      // 50000
    int E = in_sizes[1] / 2;      // 640000
    const int* srcp = edges;
    const int* dstp = edges + E;

    __half *h0, *meanb, *tb;
    float *shrt;
    cudaGetSymbolAddress((void**)&h0,    g_h0);
    cudaGetSymbolAddress((void**)&shrt,  g_short);
    cudaGetSymbolAddress((void**)&meanb, g_mean);
    cudaGetSymbolAddress((void**)&tb,    g_t);

    const int MM_SMEM = (64 + 128) * KPAD * (int)sizeof(__half);  // 52224 B
    cudaFuncSetAttribute(mm_dual_kernel, cudaFuncAttributeMaxDynamicSharedMemorySize, MM_SMEM);
    cudaFuncSetAttribute(mm_sage_kernel<true>,  cudaFuncAttributeMaxDynamicSharedMemorySize, MM_SMEM);
    cudaFuncSetAttribute(mm_sage_kernel<false>, cudaFuncAttributeMaxDynamicSharedMemorySize, MM_SMEM);

    int nblk = (M + 63) / 64;
    int wgrid = (M * 32 + 255) / 256;
    int nb256 = (M + 255) / 256;
    int egrid4 = (E + 1023) / 1024;

    // CSR build (shared by both SAGE layers)
    zero_kernel<<<nb256, 256>>>(M);
    hist_kernel<<<egrid4, 256>>>(dstp, E);
    scan_lookback_kernel<<<nb256, 256>>>(M);
    fill_kernel<<<egrid4, 256>>>(srcp, dstp, E);

    // h0 = gelu(x @ dp_w^T + dp_b) [fp16] ; shortcut = x @ sc_w^T + sc_b [fp32]
    mm_dual_kernel<<<nblk, 256, MM_SMEM>>>(x, dp_w, dp_b, sc_w, sc_b, h0, shrt, M);

    // SAGE 1 + LN + GELU fused -> h1 (fp16)
    agg_kernel<<<wgrid, 256>>>(h0, meanb, M);
    mm_sage_kernel<true><<<nblk, 256, MM_SMEM>>>(meanb, g1_lw, h0, g1_rw, g1_lb,
                                                 n1_g, n1_b, nullptr, tb, M);

    // SAGE 2 + LN + shortcut + GELU fused -> out (fp32)
    agg_kernel<<<wgrid, 256>>>(tb, meanb, M);
    mm_sage_kernel<false><<<nblk, 256, MM_SMEM>>>(meanb, g2_lw, tb, g2_rw, g2_lb,
                                                  n2_g, n2_b, shrt, out, M);
}

// round 8
// speedup vs baseline: 3.0691x; 1.0727x over previous
#include <cuda_runtime.h>
#include <cuda_fp16.h>
#include <math.h>

#define D 128
#define NN 50000
#define NE 640000
#define MMPAD 132
#define KPAD 136   // halves per row in fp16 staging (128 + 8 pad)

// ---- scratch (device globals: allocation-free) ----
__device__ __half g_h0[NN * D];     // h0 (fp16)
__device__ float  g_short[NN * D];  // shortcut (fp32: feeds output directly)
__device__ __half g_mean[NN * D];   // mean aggregation buffer (fp16)
__device__ __half g_t[NN * D];      // h1 (fp16)
__device__ __half g_w16[4][D * D];  // fp16 copies of dp_w, sc_w, g1_lw/rw pairs etc. (indexed at launch)
__device__ __half g_w16b[2][D * D]; // second SAGE layer weights
__device__ int    g_deg[NN];
__device__ int    g_cursor[NN];
__device__ int    g_rp[NN + 1];
__device__ int    g_col[NE];
__device__ unsigned long long g_desc[256];   // lookback descriptors

__device__ __forceinline__ float gelu_f(float x) {
    return 0.5f * x * (1.0f + erff(x * 0.70710678118654752f));
}

__device__ __forceinline__ unsigned f2h2(float a, float b) {
    __half2 h = __floats2half2_rn(a, b);
    return *(unsigned*)&h;
}

__device__ __forceinline__ void mma_f16(float* c, const unsigned* a, const unsigned* b) {
    asm volatile(
        "mma.sync.aligned.m16n8k16.row.col.f32.f16.f16.f32 "
        "{%0,%1,%2,%3},{%4,%5,%6,%7},{%8,%9},{%0,%1,%2,%3};"
        : "+f"(c[0]), "+f"(c[1]), "+f"(c[2]), "+f"(c[3])
        : "r"(a[0]), "r"(a[1]), "r"(a[2]), "r"(a[3]), "r"(b[0]), "r"(b[1]));
}

// ---------------- one-time weight fp32 -> fp16 conversion ----------------
// 6 matrices of D*D: dp_w, sc_w, g1_lw, g1_rw, g2_lw, g2_rw
__global__ void wconv_kernel(const float* __restrict__ w0, const float* __restrict__ w1,
                             const float* __restrict__ w2, const float* __restrict__ w3,
                             const float* __restrict__ w4, const float* __restrict__ w5) {
    int idx = blockIdx.x * blockDim.x + threadIdx.x;   // 0 .. 6*16384/2 - 1 (half2 grain)
    int mat = idx / (D * D / 2);
    int off = (idx % (D * D / 2)) * 2;
    const float* srcs[6] = {w0, w1, w2, w3, w4, w5};
    __half* dsts[6] = {g_w16[0], g_w16[1], g_w16[2], g_w16[3], g_w16b[0], g_w16b[1]};
    if (mat < 6) {
        float2 v = *(const float2*)(srcs[mat] + off);
        *(unsigned*)(dsts[mat] + off) = f2h2(v.x, v.y);
    }
}

// ---------------- CSR build ----------------
__global__ void zero_kernel(int n) {
    int i = blockIdx.x * blockDim.x + threadIdx.x;
    if (i < n) g_deg[i] = 0;
    if (i < 256) g_desc[i] = 0ULL;
}

__global__ void hist_kernel(const int* __restrict__ dst, int e_cnt) {
    int base = (blockIdx.x * blockDim.x + threadIdx.x) * 2;
    if (base + 2 <= e_cnt) {
        int2 d = *(const int2*)(dst + base);
        atomicAdd(&g_deg[d.x], 1);
        atomicAdd(&g_deg[d.y], 1);
    } else if (base < e_cnt) {
        atomicAdd(&g_deg[dst[base]], 1);
    }
}

// single-pass scan with warp-parallel decoupled lookback
__global__ void scan_lookback_kernel(int n) {
    __shared__ int wsum[8];
    __shared__ int s_total;
    __shared__ int s_excl;
    int tid = threadIdx.x, lane = tid & 31, wid = tid >> 5;
    int bid = blockIdx.x;
    int i = bid * 256 + tid;
    int v = (i < n) ? g_deg[i] : 0;
    int x = v;
    #pragma unroll
    for (int off = 1; off < 32; off <<= 1) {
        int t = __shfl_up_sync(0xFFFFFFFFu, x, off);
        if (lane >= off) x += t;
    }
    if (lane == 31) wsum[wid] = x;
    __syncthreads();
    if (tid < 32) {
        int w = (tid < 8) ? wsum[tid] : 0;
        #pragma unroll
        for (int off = 1; off < 8; off <<= 1) {
            int t = __shfl_up_sync(0xFFFFFFFFu, w, off);
            if (tid >= off) w += t;
        }
        if (tid < 8) wsum[tid] = w;
    }
    __syncthreads();
    int incl = x + ((wid > 0) ? wsum[wid - 1] : 0);
    if (tid == 255) { s_total = incl; }
    __syncthreads();
    int total = s_total;

    if (tid == 0) {
        __threadfence();
        unsigned long long st = (bid == 0) ? (2ULL << 32) : (1ULL << 32);
        atomicExch(&g_desc[bid], st | (unsigned)total);
        if (bid == 0) s_excl = 0;
    }
    if (bid > 0 && wid == 0) {
        int j = bid - 1 - lane;
        long ex = 0;
        while (true) {
            unsigned long long d;
            unsigned st;
            if (j >= 0) {
                do { d = atomicAdd(&g_desc[j], 0ULL); st = (unsigned)(d >> 32); } while (st == 0);
            } else {
                d = (2ULL << 32); st = 2u;
            }
            unsigned mask = __ballot_sync(0xFFFFFFFFu, st == 2u);
            if (mask) {
                int firstP = __ffs(mask) - 1;
                unsigned contrib = (lane <= firstP) ? (unsigned)d : 0u;
                #pragma unroll
                for (int off = 16; off; off >>= 1)
                    contrib += __shfl_xor_sync(0xFFFFFFFFu, contrib, off);
                ex += (long)contrib;
                break;
            } else {
                unsigned contrib = (unsigned)d;
                #pragma unroll
                for (int off = 16; off; off >>= 1)
                    contrib += __shfl_xor_sync(0xFFFFFFFFu, contrib, off);
                ex += (long)contrib;
                j -= 32;
            }
        }
        if (lane == 0) {
            __threadfence();
            atomicExch(&g_desc[bid], (2ULL << 32) | (unsigned)(ex + total));
            s_excl = (int)ex;
        }
    }
    __syncthreads();
    int off = s_excl;
    if (i < n) {
        int gincl = incl + off;
        g_rp[i + 1] = gincl;
        g_cursor[i] = gincl - v;
    }
    if (i == 0) g_rp[0] = 0;
}

__global__ void fill_kernel(const int* __restrict__ src, const int* __restrict__ dst, int e_cnt) {
    int base = (blockIdx.x * blockDim.x + threadIdx.x) * 2;
    if (base + 2 <= e_cnt) {
        int2 s = *(const int2*)(src + base);
        int2 d = *(const int2*)(dst + base);
        g_col[atomicAdd(&g_cursor[d.x], 1)] = s.x;
        g_col[atomicAdd(&g_cursor[d.y], 1)] = s.y;
    } else if (base < e_cnt) {
        int dd = dst[base];
        int p = atomicAdd(&g_cursor[dd], 1);
        g_col[p] = src[base];
    }
}

// ---------------- mean aggregation: warp per destination node (fp16 rows) ----------------
__global__ void agg_kernel(const __half* __restrict__ h, __half* __restrict__ meanout, int n) {
    int w = (int)((blockIdx.x * blockDim.x + threadIdx.x) >> 5);
    int lane = threadIdx.x & 31;
    if (w >= n) return;
    int s = g_rp[w], e = g_rp[w + 1];
    float a0 = 0.f, a1 = 0.f, a2 = 0.f, a3 = 0.f;
    for (int i = s; i < e; i++) {
        int srcn = __ldg(&g_col[i]);
        uint2 u = __ldg((const uint2*)(h + (size_t)srcn * D) + lane);
        float2 f0 = __half22float2(*(__half2*)&u.x);
        float2 f1 = __half22float2(*(__half2*)&u.y);
        a0 += f0.x; a1 += f0.y; a2 += f1.x; a3 += f1.y;
    }
    float inv = 1.0f / (float)max(e - s, 1);
    uint2 o;
    o.x = f2h2(a0 * inv, a1 * inv);
    o.y = f2h2(a2 * inv, a3 * inv);
    *((uint2*)(meanout + (size_t)w * D) + lane) = o;
}

// ---------------- staging helpers ----------------
// fp32 source -> half2 smem (only for x in mm_dual)
__device__ __forceinline__ void stage_A(__half* as, const float* A, int m0, int M, int tid) {
    #pragma unroll
    for (int i = 0; i < 8; i++) {
        int idx = tid + i * 256;
        int row = idx >> 5;
        int c4  = (idx & 31) * 4;
        int gm = m0 + row;
        float4 v = (gm < M) ? __ldg((const float4*)(A + (size_t)gm * D + c4))
                            : make_float4(0.f, 0.f, 0.f, 0.f);
        uint2 u = make_uint2(f2h2(v.x, v.y), f2h2(v.z, v.w));
        *(uint2*)(&as[row * KPAD + c4]) = u;
    }
}
// fp16 source -> smem (straight copy), 64 rows
__device__ __forceinline__ void stage_Ah(__half* as, const __half* A, int m0, int M, int tid) {
    #pragma unroll
    for (int i = 0; i < 4; i++) {
        int idx = tid + i * 256;        // 0..1023
        int row = idx >> 4;
        int c8  = (idx & 15) * 8;
        int gm = m0 + row;
        uint4 u = (gm < M) ? __ldg((const uint4*)(A + (size_t)gm * D + c8))
                           : make_uint4(0u, 0u, 0u, 0u);
        *(uint4*)(&as[row * KPAD + c8]) = u;
    }
}
// fp16 weight -> smem (straight copy), 128 rows
__device__ __forceinline__ void stage_Wh(__half* ws, const __half* W, int tid) {
    #pragma unroll
    for (int i = 0; i < 8; i++) {
        int idx = tid + i * 256;        // 0..2047
        int row = idx >> 4;
        int c8  = (idx & 15) * 8;
        uint4 u = __ldg((const uint4*)(W + (size_t)row * D + c8));
        *(uint4*)(&ws[row * KPAD + c8]) = u;
    }
}

__device__ __forceinline__ void load_afr(unsigned* afr, const __half* as, int ar, int k, int qc) {
    afr[0] = *(const unsigned*)&as[ar * KPAD + k + 2 * qc];
    afr[1] = *(const unsigned*)&as[(ar + 8) * KPAD + k + 2 * qc];
    afr[2] = *(const unsigned*)&as[ar * KPAD + k + 2 * qc + 8];
    afr[3] = *(const unsigned*)&as[(ar + 8) * KPAD + k + 2 * qc + 8];
}
__device__ __forceinline__ void load_bfr(unsigned* bfr, const __half* ws, int bc, int k, int qc) {
    bfr[0] = *(const unsigned*)&ws[bc * KPAD + k + 2 * qc];
    bfr[1] = *(const unsigned*)&ws[bc * KPAD + k + 2 * qc + 8];
}

// ---------------- mm_dual: out0(h0,fp16) = gelu(A@W0^T+b0), out1(shortcut,fp32) = A@W1^T+b1 ----------------
__global__ __launch_bounds__(256, 2)
void mm_dual_kernel(const float* __restrict__ A,
                    const __half* __restrict__ W0, const float* __restrict__ b0v,
                    const __half* __restrict__ W1, const float* __restrict__ b1v,
                    __half* __restrict__ out0, float* __restrict__ out1, int M) {
    extern __shared__ __half smemh[];
    __half* as = smemh;
    __half* ws = smemh + 64 * KPAD;
    int tid = threadIdx.x, lane = tid & 31, wid = tid >> 5;
    int wm = wid & 1, wn = wid >> 1;
    int m0 = blockIdx.x * 64;
    int qr = lane >> 2, qc = lane & 3;

    float acc[2][2][4][4];
    #pragma unroll
    for (int w = 0; w < 2; w++)
        #pragma unroll
        for (int i = 0; i < 2; i++)
            #pragma unroll
            for (int j = 0; j < 4; j++)
                #pragma unroll
                for (int k = 0; k < 4; k++) acc[w][i][j][k] = 0.f;

    stage_A(as, A, m0, M, tid);
    #pragma unroll
    for (int w = 0; w < 2; w++) {
        if (w) __syncthreads();
        stage_Wh(ws, w ? W1 : W0, tid);
        __syncthreads();
        #pragma unroll
        for (int ks = 0; ks < 8; ks++) {
            int k = ks * 16;
            unsigned afr[2][4], bfr[4][2];
            #pragma unroll
            for (int m = 0; m < 2; m++)
                load_afr(afr[m], as, wm * 32 + m * 16 + qr, k, qc);
            #pragma unroll
            for (int n = 0; n < 4; n++)
                load_bfr(bfr[n], ws, wn * 32 + n * 8 + qr, k, qc);
            #pragma unroll
            for (int m = 0; m < 2; m++)
                #pragma unroll
                for (int n = 0; n < 4; n++)
                    mma_f16(acc[w][m][n], afr[m], bfr[n]);
        }
    }

    int cpair = qc * 2;
    #pragma unroll
    for (int n = 0; n < 4; n++) {
        int col = wn * 32 + n * 8 + cpair;
        float b00 = __ldg(b0v + col), b01 = __ldg(b0v + col + 1);
        float b10 = __ldg(b1v + col), b11 = __ldg(b1v + col + 1);
        #pragma unroll
        for (int m = 0; m < 2; m++) {
            int gr = m0 + wm * 32 + m * 16 + qr;
            if (gr < M) {
                *(unsigned*)(out0 + (size_t)gr * D + col) =
                    f2h2(gelu_f(acc[0][m][n][0] + b00), gelu_f(acc[0][m][n][1] + b01));
                float2 o1 = make_float2(acc[1][m][n][0] + b10, acc[1][m][n][1] + b11);
                *(float2*)(out1 + (size_t)gr * D + col) = o1;
            }
            if (gr + 8 < M) {
                *(unsigned*)(out0 + (size_t)(gr + 8) * D + col) =
                    f2h2(gelu_f(acc[0][m][n][2] + b00), gelu_f(acc[0][m][n][3] + b01));
                float2 o1 = make_float2(acc[1][m][n][2] + b10, acc[1][m][n][3] + b11);
                *(float2*)(out1 + (size_t)(gr + 8) * D + col) = o1;
            }
        }
    }
}

// ---------------- mm_sage: out = gelu( LN( A0@W0^T + A1@W1^T + bias ) [+ sc] ) ----------------
template <bool OUT_HALF>
__global__ __launch_bounds__(256, 3)
void mm_sage_kernel(const __half* __restrict__ A0, const __half* __restrict__ W0,
                    const __half* __restrict__ A1, const __half* __restrict__ W1,
                    const float* __restrict__ bias,
                    const float* __restrict__ gamma, const float* __restrict__ beta,
                    const float* __restrict__ sc,
                    void* __restrict__ outp, int M) {
    extern __shared__ __half smemh[];
    __half* as = smemh;
    __half* ws = smemh + 64 * KPAD;
    int tid = threadIdx.x, lane = tid & 31, wid = tid >> 5;
    int wm = wid & 1, wn = wid >> 1;
    int m0 = blockIdx.x * 64;
    int qr = lane >> 2, qc = lane & 3;

    float acc[2][4][4];
    #pragma unroll
    for (int i = 0; i < 2; i++)
        #pragma unroll
        for (int j = 0; j < 4; j++)
            #pragma unroll
            for (int k = 0; k < 4; k++) acc[i][j][k] = 0.f;

    #pragma unroll
    for (int ph = 0; ph < 2; ph++) {
        if (ph) __syncthreads();
        stage_Ah(as, ph ? A1 : A0, m0, M, tid);
        stage_Wh(ws, ph ? W1 : W0, tid);
        __syncthreads();
        #pragma unroll
        for (int ks = 0; ks < 8; ks++) {
            int k = ks * 16;
            unsigned afr[2][4], bfr[4][2];
            #pragma unroll
            for (int m = 0; m < 2; m++)
                load_afr(afr[m], as, wm * 32 + m * 16 + qr, k, qc);
            #pragma unroll
            for (int n = 0; n < 4; n++)
                load_bfr(bfr[n], ws, wn * 32 + n * 8 + qr, k, qc);
            #pragma unroll
            for (int m = 0; m < 2; m++)
                #pragma unroll
                for (int n = 0; n < 4; n++)
                    mma_f16(acc[m][n], afr[m], bfr[n]);
        }
    }

    // spill tile (+bias) to smem as fp32, then warp-per-row LN epilogue
    float* os = (float*)smemh;   // reuse, [64][MMPAD] fp32 (33792 B <= 52224 B)
    __syncthreads();
    int cpair = qc * 2;
    #pragma unroll
    for (int n = 0; n < 4; n++) {
        int col = wn * 32 + n * 8 + cpair;
        float b0 = __ldg(bias + col), b1 = __ldg(bias + col + 1);
        #pragma unroll
        for (int m = 0; m < 2; m++) {
            int r = wm * 32 + m * 16 + qr;
            os[r * MMPAD + col]           = acc[m][n][0] + b0;
            os[r * MMPAD + col + 1]       = acc[m][n][1] + b1;
            os[(r + 8) * MMPAD + col]     = acc[m][n][2] + b0;
            os[(r + 8) * MMPAD + col + 1] = acc[m][n][3] + b1;
        }
    }
    __syncthreads();

    float4 g = __ldg((const float4*)gamma + lane);
    float4 bb = __ldg((const float4*)beta + lane);
    for (int rr = wid; rr < 64; rr += 8) {
        int gr = m0 + rr;
        if (gr >= M) break;
        float4 v = *(const float4*)&os[rr * MMPAD + lane * 4];
        float s = v.x + v.y + v.z + v.w;
        #pragma unroll
        for (int off = 16; off; off >>= 1) s += __shfl_xor_sync(0xFFFFFFFFu, s, off);
        float mu = s * (1.0f / 128.0f);
        float dx = v.x - mu, dy = v.y - mu, dz = v.z - mu, dw = v.w - mu;
        float q = dx * dx + dy * dy + dz * dz + dw * dw;
        #pragma unroll
        for (int off = 16; off; off >>= 1) q += __shfl_xor_sync(0xFFFFFFFFu, q, off);
        float r = rsqrtf(q * (1.0f / 128.0f) + 1e-5f);
        float4 o;
        o.x = dx * r * g.x + bb.x;
        o.y = dy * r * g.y + bb.y;
        o.z = dz * r * g.z + bb.z;
        o.w = dw * r * g.w + bb.w;
        if (sc != nullptr) {
            float4 scv = __ldg((const float4*)(sc + (size_t)gr * D) + lane);
            o.x += scv.x; o.y += scv.y; o.z += scv.z; o.w += scv.w;
        }
        o.x = gelu_f(o.x); o.y = gelu_f(o.y); o.z = gelu_f(o.z); o.w = gelu_f(o.w);
        if (OUT_HALF) {
            __half* oh = (__half*)outp;
            uint2 u;
            u.x = f2h2(o.x, o.y);
            u.y = f2h2(o.z, o.w);
            *((uint2*)(oh + (size_t)gr * D) + lane) = u;
        } else {
            float* of = (float*)outp;
            *(float4*)(of + (size_t)gr * D + lane * 4) = o;
        }
    }
}

extern "C" void kernel_launch(void* const* d_in, const int* in_sizes, int n_in,
                              void* d_out, int out_size) {
    const float* x     = (const float*)d_in[0];
    const int*   edges = (const int*)  d_in[1];
    const float* dp_w  = (const float*)d_in[2];
    const float* dp_b  = (const float*)d_in[3];
    const float* sc_w  = (const float*)d_in[4];
    const float* sc_b  = (const float*)d_in[5];
    const float* g1_lw = (const float*)d_in[6];
    const float* g1_lb = (const float*)d_in[7];
    const float* g1_rw = (const float*)d_in[8];
    const float* n1_g  = (const float*)d_in[9];
    const float* n1_b  = (const float*)d_in[10];
    const float* g2_lw = (const float*)d_in[11];
    const float* g2_lb = (const float*)d_in[12];
    const float* g2_rw = (const float*)d_in[13];
    const float* n2_g  = (const float*)d_in[14];
    const float* n2_b  = (const float*)d_in[15];
    float* out = (float*)d_out;

    int M = in_sizes[0] / D;      // 50000
    int E = in_sizes[1] / 2;      // 640000
    const int* srcp = edges;
    const int* dstp = edges + E;

    __half *h0, *meanb, *tb, *w16, *w16b;
    float *shrt;
    cudaGetSymbolAddress((void**)&h0,    g_h0);
    cudaGetSymbolAddress((void**)&shrt,  g_short);
    cudaGetSymbolAddress((void**)&meanb, g_mean);
    cudaGetSymbolAddress((void**)&tb,    g_t);
    cudaGetSymbolAddress((void**)&w16,   g_w16);
    cudaGetSymbolAddress((void**)&w16b,  g_w16b);
    __half* dpw_h  = w16 + 0 * D * D;
    __half* scw_h  = w16 + 1 * D * D;
    __half* g1lw_h = w16 + 2 * D * D;
    __half* g1rw_h = w16 + 3 * D * D;
    __half* g2lw_h = w16b + 0 * D * D;
    __half* g2rw_h = w16b + 1 * D * D;

    const int MM_SMEM = (64 + 128) * KPAD * (int)sizeof(__half);  // 52224 B
    cudaFuncSetAttribute(mm_dual_kernel, cudaFuncAttributeMaxDynamicSharedMemorySize, MM_SMEM);
    cudaFuncSetAttribute(mm_sage_kernel<true>,  cudaFuncAttributeMaxDynamicSharedMemorySize, MM_SMEM);
    cudaFuncSetAttribute(mm_sage_kernel<false>, cudaFuncAttributeMaxDynamicSharedMemorySize, MM_SMEM);

    int nblk = (M + 63) / 64;
    int wgrid = (M * 32 + 255) / 256;
    int nb256 = (M + 255) / 256;
    int egrid2 = (E + 511) / 512;

    // weights -> fp16 (once per launch; tiny)
    wconv_kernel<<<(6 * D * D / 2 + 255) / 256, 256>>>(dp_w, sc_w, g1_lw, g1_rw, g2_lw, g2_rw);

    // CSR build (shared by both SAGE layers)
    zero_kernel<<<nb256, 256>>>(M);
    hist_kernel<<<egrid2, 256>>>(dstp, E);
    scan_lookback_kernel<<<nb256, 256>>>(M);
    fill_kernel<<<egrid2, 256>>>(srcp, dstp, E);

    // h0 = gelu(x @ dp_w^T + dp_b) [fp16] ; shortcut = x @ sc_w^T + sc_b [fp32]
    mm_dual_kernel<<<nblk, 256, MM_SMEM>>>(x, dpw_h, dp_b, scw_h, sc_b, h0, shrt, M);

    // SAGE 1 + LN + GELU fused -> h1 (fp16)
    agg_kernel<<<wgrid, 256>>>(h0, meanb, M);
    mm_sage_kernel<true><<<nblk, 256, MM_SMEM>>>(meanb, g1lw_h, h0, g1rw_h, g1_lb,
                                                 n1_g, n1_b, nullptr, tb, M);

    // SAGE 2 + LN + shortcut + GELU fused -> out (fp32)
    agg_kernel<<<wgrid, 256>>>(tb, meanb, M);
    mm_sage_kernel<false><<<nblk, 256, MM_SMEM>>>(meanb, g2lw_h, tb, g2rw_h, g2_lb,
                                                  n2_g, n2_b, shrt, out, M);
}

// round 9
// speedup vs baseline: 3.1448x; 1.0247x over previous
#include <cuda_runtime.h>
#include <cuda_fp16.h>
#include <math.h>

#define D 128
#define NN 50000
#define NE 640000
#define MMPAD 132
#define KPAD 136   // halves per row in fp16 staging (128 + 8 pad)

// ---- scratch (device globals: allocation-free) ----
__device__ __half g_h0[NN * D];     // h0 (fp16)
__device__ float  g_short[NN * D];  // shortcut (fp32: feeds output directly)
__device__ __half g_mean[NN * D];   // mean aggregation buffer (fp16)
__device__ __half g_t[NN * D];      // h1 (fp16)
__device__ __half g_w16[4][D * D];  // fp16 weights: dp_w, sc_w, g1_lw, g1_rw
__device__ __half g_w16b[2][D * D]; // fp16 weights: g2_lw, g2_rw
__device__ int    g_deg[NN];
__device__ int    g_cursor[NN];
__device__ int    g_rp[NN + 1];
__device__ int    g_col[NE];
__device__ unsigned long long g_desc[256];   // lookback descriptors

// ---- host-side stream/event for forked graph capture (created once at load;
//      not device memory allocation) ----
struct ForkCtx {
    cudaStream_t side;
    cudaEvent_t evFork, evJoin;
    ForkCtx() {
        cudaStreamCreateWithFlags(&side, cudaStreamNonBlocking);
        cudaEventCreateWithFlags(&evFork, cudaEventDisableTiming);
        cudaEventCreateWithFlags(&evJoin, cudaEventDisableTiming);
    }
};
static ForkCtx g_fork;

__device__ __forceinline__ float gelu_f(float x) {
    return 0.5f * x * (1.0f + erff(x * 0.70710678118654752f));
}

__device__ __forceinline__ unsigned f2h2(float a, float b) {
    __half2 h = __floats2half2_rn(a, b);
    return *(unsigned*)&h;
}

__device__ __forceinline__ void mma_f16(float* c, const unsigned* a, const unsigned* b) {
    asm volatile(
        "mma.sync.aligned.m16n8k16.row.col.f32.f16.f16.f32 "
        "{%0,%1,%2,%3},{%4,%5,%6,%7},{%8,%9},{%0,%1,%2,%3};"
        : "+f"(c[0]), "+f"(c[1]), "+f"(c[2]), "+f"(c[3])
        : "r"(a[0]), "r"(a[1]), "r"(a[2]), "r"(a[3]), "r"(b[0]), "r"(b[1]));
}

// ---------------- one-time weight fp32 -> fp16 conversion ----------------
__global__ void wconv_kernel(const float* __restrict__ w0, const float* __restrict__ w1,
                             const float* __restrict__ w2, const float* __restrict__ w3,
                             const float* __restrict__ w4, const float* __restrict__ w5) {
    int idx = blockIdx.x * blockDim.x + threadIdx.x;
    int mat = idx / (D * D / 2);
    int off = (idx % (D * D / 2)) * 2;
    const float* srcs[6] = {w0, w1, w2, w3, w4, w5};
    __half* dsts[6] = {g_w16[0], g_w16[1], g_w16[2], g_w16[3], g_w16b[0], g_w16b[1]};
    if (mat < 6) {
        float2 v = *(const float2*)(srcs[mat] + off);
        *(unsigned*)(dsts[mat] + off) = f2h2(v.x, v.y);
    }
}

// ---------------- CSR build ----------------
__global__ void hist_kernel(const int* __restrict__ dst, int e_cnt) {
    int base = (blockIdx.x * blockDim.x + threadIdx.x) * 2;
    if (base + 2 <= e_cnt) {
        int2 d = *(const int2*)(dst + base);
        atomicAdd(&g_deg[d.x], 1);
        atomicAdd(&g_deg[d.y], 1);
    } else if (base < e_cnt) {
        atomicAdd(&g_deg[dst[base]], 1);
    }
}

// single-pass scan with warp-parallel decoupled lookback
__global__ void scan_lookback_kernel(int n) {
    __shared__ int wsum[8];
    __shared__ int s_total;
    __shared__ int s_excl;
    int tid = threadIdx.x, lane = tid & 31, wid = tid >> 5;
    int bid = blockIdx.x;
    int i = bid * 256 + tid;
    int v = (i < n) ? g_deg[i] : 0;
    int x = v;
    #pragma unroll
    for (int off = 1; off < 32; off <<= 1) {
        int t = __shfl_up_sync(0xFFFFFFFFu, x, off);
        if (lane >= off) x += t;
    }
    if (lane == 31) wsum[wid] = x;
    __syncthreads();
    if (tid < 32) {
        int w = (tid < 8) ? wsum[tid] : 0;
        #pragma unroll
        for (int off = 1; off < 8; off <<= 1) {
            int t = __shfl_up_sync(0xFFFFFFFFu, w, off);
            if (tid >= off) w += t;
        }
        if (tid < 8) wsum[tid] = w;
    }
    __syncthreads();
    int incl = x + ((wid > 0) ? wsum[wid - 1] : 0);
    if (tid == 255) { s_total = incl; }
    __syncthreads();
    int total = s_total;

    if (tid == 0) {
        __threadfence();
        unsigned long long st = (bid == 0) ? (2ULL << 32) : (1ULL << 32);
        atomicExch(&g_desc[bid], st | (unsigned)total);
        if (bid == 0) s_excl = 0;
    }
    if (bid > 0 && wid == 0) {
        int j = bid - 1 - lane;
        long ex = 0;
        while (true) {
            unsigned long long d;
            unsigned st;
            if (j >= 0) {
                do { d = atomicAdd(&g_desc[j], 0ULL); st = (unsigned)(d >> 32); } while (st == 0);
            } else {
                d = (2ULL << 32); st = 2u;
            }
            unsigned mask = __ballot_sync(0xFFFFFFFFu, st == 2u);
            if (mask) {
                int firstP = __ffs(mask) - 1;
                unsigned contrib = (lane <= firstP) ? (unsigned)d : 0u;
                #pragma unroll
                for (int off = 16; off; off >>= 1)
                    contrib += __shfl_xor_sync(0xFFFFFFFFu, contrib, off);
                ex += (long)contrib;
                break;
            } else {
                unsigned contrib = (unsigned)d;
                #pragma unroll
                for (int off = 16; off; off >>= 1)
                    contrib += __shfl_xor_sync(0xFFFFFFFFu, contrib, off);
                ex += (long)contrib;
                j -= 32;
            }
        }
        if (lane == 0) {
            __threadfence();
            atomicExch(&g_desc[bid], (2ULL << 32) | (unsigned)(ex + total));
            s_excl = (int)ex;
        }
    }
    __syncthreads();
    int off = s_excl;
    if (i < n) {
        int gincl = incl + off;
        g_rp[i + 1] = gincl;
        g_cursor[i] = gincl - v;
    }
    if (i == 0) g_rp[0] = 0;
}

__global__ void fill_kernel(const int* __restrict__ src, const int* __restrict__ dst, int e_cnt) {
    int base = (blockIdx.x * blockDim.x + threadIdx.x) * 2;
    if (base + 2 <= e_cnt) {
        int2 s = *(const int2*)(src + base);
        int2 d = *(const int2*)(dst + base);
        g_col[atomicAdd(&g_cursor[d.x], 1)] = s.x;
        g_col[atomicAdd(&g_cursor[d.y], 1)] = s.y;
    } else if (base < e_cnt) {
        int dd = dst[base];
        int p = atomicAdd(&g_cursor[dd], 1);
        g_col[p] = src[base];
    }
}

// ---------------- mean aggregation: warp per destination node (fp16 rows) ----------------
__global__ void agg_kernel(const __half* __restrict__ h, __half* __restrict__ meanout, int n) {
    int w = (int)((blockIdx.x * blockDim.x + threadIdx.x) >> 5);
    int lane = threadIdx.x & 31;
    if (w >= n) return;
    int s = g_rp[w], e = g_rp[w + 1];
    float a0 = 0.f, a1 = 0.f, a2 = 0.f, a3 = 0.f;
    for (int i = s; i < e; i++) {
        int srcn = __ldg(&g_col[i]);
        uint2 u = __ldg((const uint2*)(h + (size_t)srcn * D) + lane);
        float2 f0 = __half22float2(*(__half2*)&u.x);
        float2 f1 = __half22float2(*(__half2*)&u.y);
        a0 += f0.x; a1 += f0.y; a2 += f1.x; a3 += f1.y;
    }
    float inv = 1.0f / (float)max(e - s, 1);
    uint2 o;
    o.x = f2h2(a0 * inv, a1 * inv);
    o.y = f2h2(a2 * inv, a3 * inv);
    *((uint2*)(meanout + (size_t)w * D) + lane) = o;
}

// ---------------- staging helpers ----------------
__device__ __forceinline__ void stage_A(__half* as, const float* A, int m0, int M, int tid) {
    #pragma unroll
    for (int i = 0; i < 8; i++) {
        int idx = tid + i * 256;
        int row = idx >> 5;
        int c4  = (idx & 31) * 4;
        int gm = m0 + row;
        float4 v = (gm < M) ? __ldg((const float4*)(A + (size_t)gm * D + c4))
                            : make_float4(0.f, 0.f, 0.f, 0.f);
        uint2 u = make_uint2(f2h2(v.x, v.y), f2h2(v.z, v.w));
        *(uint2*)(&as[row * KPAD + c4]) = u;
    }
}
__device__ __forceinline__ void stage_Ah(__half* as, const __half* A, int m0, int M, int tid) {
    #pragma unroll
    for (int i = 0; i < 4; i++) {
        int idx = tid + i * 256;
        int row = idx >> 4;
        int c8  = (idx & 15) * 8;
        int gm = m0 + row;
        uint4 u = (gm < M) ? __ldg((const uint4*)(A + (size_t)gm * D + c8))
                           : make_uint4(0u, 0u, 0u, 0u);
        *(uint4*)(&as[row * KPAD + c8]) = u;
    }
}
__device__ __forceinline__ void stage_Wh(__half* ws, const __half* W, int tid) {
    #pragma unroll
    for (int i = 0; i < 8; i++) {
        int idx = tid + i * 256;
        int row = idx >> 4;
        int c8  = (idx & 15) * 8;
        uint4 u = __ldg((const uint4*)(W + (size_t)row * D + c8));
        *(uint4*)(&ws[row * KPAD + c8]) = u;
    }
}

__device__ __forceinline__ void load_afr(unsigned* afr, const __half* as, int ar, int k, int qc) {
    afr[0] = *(const unsigned*)&as[ar * KPAD + k + 2 * qc];
    afr[1] = *(const unsigned*)&as[(ar + 8) * KPAD + k + 2 * qc];
    afr[2] = *(const unsigned*)&as[ar * KPAD + k + 2 * qc + 8];
    afr[3] = *(const unsigned*)&as[(ar + 8) * KPAD + k + 2 * qc + 8];
}
__device__ __forceinline__ void load_bfr(unsigned* bfr, const __half* ws, int bc, int k, int qc) {
    bfr[0] = *(const unsigned*)&ws[bc * KPAD + k + 2 * qc];
    bfr[1] = *(const unsigned*)&ws[bc * KPAD + k + 2 * qc + 8];
}

// ---------------- mm_dual: out0(h0,fp16) = gelu(A@W0^T+b0), out1(shortcut,fp32) = A@W1^T+b1 ----------------
__global__ __launch_bounds__(256, 2)
void mm_dual_kernel(const float* __restrict__ A,
                    const __half* __restrict__ W0, const float* __restrict__ b0v,
                    const __half* __restrict__ W1, const float* __restrict__ b1v,
                    __half* __restrict__ out0, float* __restrict__ out1, int M) {
    extern __shared__ __half smemh[];
    __half* as = smemh;
    __half* ws = smemh + 64 * KPAD;
    int tid = threadIdx.x, lane = tid & 31, wid = tid >> 5;
    int wm = wid & 1, wn = wid >> 1;
    int m0 = blockIdx.x * 64;
    int qr = lane >> 2, qc = lane & 3;

    float acc[2][2][4][4];
    #pragma unroll
    for (int w = 0; w < 2; w++)
        #pragma unroll
        for (int i = 0; i < 2; i++)
            #pragma unroll
            for (int j = 0; j < 4; j++)
                #pragma unroll
                for (int k = 0; k < 4; k++) acc[w][i][j][k] = 0.f;

    stage_A(as, A, m0, M, tid);
    #pragma unroll
    for (int w = 0; w < 2; w++) {
        if (w) __syncthreads();
        stage_Wh(ws, w ? W1 : W0, tid);
        __syncthreads();
        #pragma unroll
        for (int ks = 0; ks < 8; ks++) {
            int k = ks * 16;
            unsigned afr[2][4], bfr[4][2];
            #pragma unroll
            for (int m = 0; m < 2; m++)
                load_afr(afr[m], as, wm * 32 + m * 16 + qr, k, qc);
            #pragma unroll
            for (int n = 0; n < 4; n++)
                load_bfr(bfr[n], ws, wn * 32 + n * 8 + qr, k, qc);
            #pragma unroll
            for (int m = 0; m < 2; m++)
                #pragma unroll
                for (int n = 0; n < 4; n++)
                    mma_f16(acc[w][m][n], afr[m], bfr[n]);
        }
    }

    int cpair = qc * 2;
    #pragma unroll
    for (int n = 0; n < 4; n++) {
        int col = wn * 32 + n * 8 + cpair;
        float b00 = __ldg(b0v + col), b01 = __ldg(b0v + col + 1);
        float b10 = __ldg(b1v + col), b11 = __ldg(b1v + col + 1);
        #pragma unroll
        for (int m = 0; m < 2; m++) {
            int gr = m0 + wm * 32 + m * 16 + qr;
            if (gr < M) {
                *(unsigned*)(out0 + (size_t)gr * D + col) =
                    f2h2(gelu_f(acc[0][m][n][0] + b00), gelu_f(acc[0][m][n][1] + b01));
                float2 o1 = make_float2(acc[1][m][n][0] + b10, acc[1][m][n][1] + b11);
                *(float2*)(out1 + (size_t)gr * D + col) = o1;
            }
            if (gr + 8 < M) {
                *(unsigned*)(out0 + (size_t)(gr + 8) * D + col) =
                    f2h2(gelu_f(acc[0][m][n][2] + b00), gelu_f(acc[0][m][n][3] + b01));
                float2 o1 = make_float2(acc[1][m][n][2] + b10, acc[1][m][n][3] + b11);
                *(float2*)(out1 + (size_t)(gr + 8) * D + col) = o1;
            }
        }
    }
}

// ---------------- mm_sage: out = gelu( LN( A0@W0^T + A1@W1^T + bias ) [+ sc] ) ----------------
template <bool OUT_HALF>
__global__ __launch_bounds__(256, 3)
void mm_sage_kernel(const __half* __restrict__ A0, const __half* __restrict__ W0,
                    const __half* __restrict__ A1, const __half* __restrict__ W1,
                    const float* __restrict__ bias,
                    const float* __restrict__ gamma, const float* __restrict__ beta,
                    const float* __restrict__ sc,
                    void* __restrict__ outp, int M) {
    extern __shared__ __half smemh[];
    __half* as = smemh;
    __half* ws = smemh + 64 * KPAD;
    int tid = threadIdx.x, lane = tid & 31, wid = tid >> 5;
    int wm = wid & 1, wn = wid >> 1;
    int m0 = blockIdx.x * 64;
    int qr = lane >> 2, qc = lane & 3;

    float acc[2][4][4];
    #pragma unroll
    for (int i = 0; i < 2; i++)
        #pragma unroll
        for (int j = 0; j < 4; j++)
            #pragma unroll
            for (int k = 0; k < 4; k++) acc[i][j][k] = 0.f;

    #pragma unroll
    for (int ph = 0; ph < 2; ph++) {
        if (ph) __syncthreads();
        stage_Ah(as, ph ? A1 : A0, m0, M, tid);
        stage_Wh(ws, ph ? W1 : W0, tid);
        __syncthreads();
        #pragma unroll
        for (int ks = 0; ks < 8; ks++) {
            int k = ks * 16;
            unsigned afr[2][4], bfr[4][2];
            #pragma unroll
            for (int m = 0; m < 2; m++)
                load_afr(afr[m], as, wm * 32 + m * 16 + qr, k, qc);
            #pragma unroll
            for (int n = 0; n < 4; n++)
                load_bfr(bfr[n], ws, wn * 32 + n * 8 + qr, k, qc);
            #pragma unroll
            for (int m = 0; m < 2; m++)
                #pragma unroll
                for (int n = 0; n < 4; n++)
                    mma_f16(acc[m][n], afr[m], bfr[n]);
        }
    }

    // spill tile (+bias) to smem as fp32, then warp-per-row LN epilogue
    float* os = (float*)smemh;   // reuse, [64][MMPAD] fp32
    __syncthreads();
    int cpair = qc * 2;
    #pragma unroll
    for (int n = 0; n < 4; n++) {
        int col = wn * 32 + n * 8 + cpair;
        float b0 = __ldg(bias + col), b1 = __ldg(bias + col + 1);
        #pragma unroll
        for (int m = 0; m < 2; m++) {
            int r = wm * 32 + m * 16 + qr;
            os[r * MMPAD + col]           = acc[m][n][0] + b0;
            os[r * MMPAD + col + 1]       = acc[m][n][1] + b1;
            os[(r + 8) * MMPAD + col]     = acc[m][n][2] + b0;
            os[(r + 8) * MMPAD + col + 1] = acc[m][n][3] + b1;
        }
    }
    __syncthreads();

    float4 g = __ldg((const float4*)gamma + lane);
    float4 bb = __ldg((const float4*)beta + lane);
    for (int rr = wid; rr < 64; rr += 8) {
        int gr = m0 + rr;
        if (gr >= M) break;
        float4 v = *(const float4*)&os[rr * MMPAD + lane * 4];
        float s = v.x + v.y + v.z + v.w;
        #pragma unroll
        for (int off = 16; off; off >>= 1) s += __shfl_xor_sync(0xFFFFFFFFu, s, off);
        float mu = s * (1.0f / 128.0f);
        float dx = v.x - mu, dy = v.y - mu, dz = v.z - mu, dw = v.w - mu;
        float q = dx * dx + dy * dy + dz * dz + dw * dw;
        #pragma unroll
        for (int off = 16; off; off >>= 1) q += __shfl_xor_sync(0xFFFFFFFFu, q, off);
        float r = rsqrtf(q * (1.0f / 128.0f) + 1e-5f);
        float4 o;
        o.x = dx * r * g.x + bb.x;
        o.y = dy * r * g.y + bb.y;
        o.z = dz * r * g.z + bb.z;
        o.w = dw * r * g.w + bb.w;
        if (sc != nullptr) {
            float4 scv = __ldg((const float4*)(sc + (size_t)gr * D) + lane);
            o.x += scv.x; o.y += scv.y; o.z += scv.z; o.w += scv.w;
        }
        o.x = gelu_f(o.x); o.y = gelu_f(o.y); o.z = gelu_f(o.z); o.w = gelu_f(o.w);
        if (OUT_HALF) {
            __half* oh = (__half*)outp;
            uint2 u;
            u.x = f2h2(o.x, o.y);
            u.y = f2h2(o.z, o.w);
            *((uint2*)(oh + (size_t)gr * D) + lane) = u;
        } else {
            float* of = (float*)outp;
            *(float4*)(of + (size_t)gr * D + lane * 4) = o;
        }
    }
}

extern "C" void kernel_launch(void* const* d_in, const int* in_sizes, int n_in,
                              void* d_out, int out_size) {
    const float* x     = (const float*)d_in[0];
    const int*   edges = (const int*)  d_in[1];
    const float* dp_w  = (const float*)d_in[2];
    const float* dp_b  = (const float*)d_in[3];
    const float* sc_w  = (const float*)d_in[4];
    const float* sc_b  = (const float*)d_in[5];
    const float* g1_lw = (const float*)d_in[6];
    const float* g1_lb = (const float*)d_in[7];
    const float* g1_rw = (const float*)d_in[8];
    const float* n1_g  = (const float*)d_in[9];
    const float* n1_b  = (const float*)d_in[10];
    const float* g2_lw = (const float*)d_in[11];
    const float* g2_lb = (const float*)d_in[12];
    const float* g2_rw = (const float*)d_in[13];
    const float* n2_g  = (const float*)d_in[14];
    const float* n2_b  = (const float*)d_in[15];
    float* out = (float*)d_out;

    int M = in_sizes[0] / D;      // 50000
    int E = in_sizes[1] / 2;      // 640000
    const int* srcp = edges;
    const int* dstp = edges + E;

    __half *h0, *meanb, *tb, *w16, *w16b;
    float *shrt;
    int *degp;
    unsigned long long *descp;
    cudaGetSymbolAddress((void**)&h0,    g_h0);
    cudaGetSymbolAddress((void**)&shrt,  g_short);
    cudaGetSymbolAddress((void**)&meanb, g_mean);
    cudaGetSymbolAddress((void**)&tb,    g_t);
    cudaGetSymbolAddress((void**)&w16,   g_w16);
    cudaGetSymbolAddress((void**)&w16b,  g_w16b);
    cudaGetSymbolAddress((void**)&degp,  g_deg);
    cudaGetSymbolAddress((void**)&descp, g_desc);
    __half* dpw_h  = w16 + 0 * D * D;
    __half* scw_h  = w16 + 1 * D * D;
    __half* g1lw_h = w16 + 2 * D * D;
    __half* g1rw_h = w16 + 3 * D * D;
    __half* g2lw_h = w16b + 0 * D * D;
    __half* g2rw_h = w16b + 1 * D * D;

    const int MM_SMEM = (64 + 128) * KPAD * (int)sizeof(__half);  // 52224 B
    cudaFuncSetAttribute(mm_dual_kernel, cudaFuncAttributeMaxDynamicSharedMemorySize, MM_SMEM);
    cudaFuncSetAttribute(mm_sage_kernel<true>,  cudaFuncAttributeMaxDynamicSharedMemorySize, MM_SMEM);
    cudaFuncSetAttribute(mm_sage_kernel<false>, cudaFuncAttributeMaxDynamicSharedMemorySize, MM_SMEM);

    int nblk = (M + 63) / 64;
    int wgrid = (M * 32 + 255) / 256;
    int nb256 = (M + 255) / 256;
    int egrid2 = (E + 511) / 512;

    cudaStream_t side = g_fork.side;

    // ---- fork: CSR build on side stream, concurrent with wconv + mm_dual ----
    cudaEventRecord(g_fork.evFork, 0);
    cudaStreamWaitEvent(side, g_fork.evFork, 0);

    cudaMemsetAsync(degp, 0, NN * sizeof(int), side);
    cudaMemsetAsync(descp, 0, 256 * sizeof(unsigned long long), side);
    hist_kernel<<<egrid2, 256, 0, side>>>(dstp, E);
    scan_lookback_kernel<<<nb256, 256, 0, side>>>(M);
    fill_kernel<<<egrid2, 256, 0, side>>>(srcp, dstp, E);
    cudaEventRecord(g_fork.evJoin, side);

    // ---- main branch: weights -> fp16, then h0/shortcut GEMM ----
    wconv_kernel<<<(6 * D * D / 2 + 255) / 256, 256>>>(dp_w, sc_w, g1_lw, g1_rw, g2_lw, g2_rw);
    mm_dual_kernel<<<nblk, 256, MM_SMEM>>>(x, dpw_h, dp_b, scw_h, sc_b, h0, shrt, M);

    // ---- join: aggregation needs both CSR and h0 ----
    cudaStreamWaitEvent(0, g_fork.evJoin, 0);

    // SAGE 1 + LN + GELU fused -> h1 (fp16)
    agg_kernel<<<wgrid, 256>>>(h0, meanb, M);
    mm_sage_kernel<true><<<nblk, 256, MM_SMEM>>>(meanb, g1lw_h, h0, g1rw_h, g1_lb,
                                                 n1_g, n1_b, nullptr, tb, M);

    // SAGE 2 + LN + shortcut + GELU fused -> out (fp32)
    agg_kernel<<<wgrid, 256>>>(tb, meanb, M);
    mm_sage_kernel<false><<<nblk, 256, MM_SMEM>>>(meanb, g2lw_h, tb, g2rw_h, g2_lb,
                                                  n2_g, n2_b, shrt, out, M);
}